// round 13
// baseline (speedup 1.0000x reference)
#include <cuda_runtime.h>
#include <mma.h>
#include <cstdint>
#include <math.h>

using namespace nvcuda;

#define Hc   224
#define Wc   224
#define HWc  (Hc * Wc)
#define Bc   2
#define MTOK (Bc * HWc)      // 100352
#define Ec   64
#define NHc  4
#define DHc  16
#define DFFc 2048

// ---------------- scratch ----------------
__device__ float g_bufA[MTOK * 64];
__device__ float g_t   [MTOK * 64];
__device__ float g_qkv [MTOK * 192];
__device__ float g_t1  [MTOK * 64];
__device__ float g_t2  [MTOK * 64];
__device__ float g_sf1 [MTOK * 32];
__device__ float g_fus [MTOK];
__device__ float g_d1  [MTOK * 64];
__device__ float g_wr  [64 * 576 + 32 * 576];

__device__ __forceinline__ float to_tf32(float x) {
    uint32_t r;
    asm("cvt.rna.tf32.f32 %0, %1;" : "=r"(r) : "f"(x));
    return __uint_as_float(r);
}
__device__ __forceinline__ float4 to_tf32_4(float4 v) {
    return make_float4(to_tf32(v.x), to_tf32(v.y), to_tf32(v.z), to_tf32(v.w));
}

#define SA 36
#define SE 68
#define FSA 76
#define BK 32
#define FBM 256
#define FFN_SMEM ((FBM * FSA + 2 * 64 * FSA + 2 * 64 * SE + FBM * SE) * 4)
#define QKV_SMEM ((256 * SE + 64 * SE) * 4)
#define OPROJ_SMEM ((128 * SE + 64 * SE) * 4)
#define SCONV_SMEM ((256 * SE) * 4)

// ============ qkv GEMM: C[M,192] = A[M,64] @ W[192,64]^T + bias, BM=256 ============
__global__ void __launch_bounds__(256)
qkv_gemm(const float* __restrict__ A, const float* __restrict__ W,
         const float* __restrict__ bias, float* __restrict__ C, int N) {
    extern __shared__ float sm[];
    float* As = sm;
    float* Ws = sm + 256 * SE;
    const int tid = threadIdx.x;
    const int warp = tid >> 5;
    const int wm = warp >> 1, wn = warp & 1;
    const size_t m0 = (size_t)blockIdx.y * 256;
    const int n0 = blockIdx.x * 64;

#pragma unroll
    for (int i = tid; i < 256 * 16; i += 256) {
        int row = i >> 4, q = i & 15;
        float4 v = *(const float4*)&A[(m0 + row) * 64 + q * 4];
        *(float4*)&As[row * SE + q * 4] = to_tf32_4(v);
    }
#pragma unroll
    for (int i = tid; i < 64 * 16; i += 256) {
        int n = i >> 4, q = i & 15;
        float4 v = *(const float4*)&W[(size_t)(n0 + n) * 64 + q * 4];
        *(float4*)&Ws[n * SE + q * 4] = to_tf32_4(v);
    }
    __syncthreads();

    wmma::fragment<wmma::accumulator, 16, 16, 8, float> acc[4][2];
#pragma unroll
    for (int i = 0; i < 4; i++)
#pragma unroll
        for (int j = 0; j < 2; j++) wmma::fill_fragment(acc[i][j], 0.f);
#pragma unroll
    for (int ks = 0; ks < 8; ks++) {
        wmma::fragment<wmma::matrix_a, 16, 16, 8, wmma::precision::tf32, wmma::row_major> a[4];
        wmma::fragment<wmma::matrix_b, 16, 16, 8, wmma::precision::tf32, wmma::col_major> b[2];
#pragma unroll
        for (int i = 0; i < 4; i++)
            wmma::load_matrix_sync(a[i], &As[(wm * 64 + i * 16) * SE + ks * 8], SE);
#pragma unroll
        for (int j = 0; j < 2; j++)
            wmma::load_matrix_sync(b[j], &Ws[(wn * 32 + j * 16) * SE + ks * 8], SE);
#pragma unroll
        for (int i = 0; i < 4; i++)
#pragma unroll
            for (int j = 0; j < 2; j++)
                wmma::mma_sync(acc[i][j], a[i], b[j], acc[i][j]);
    }
    __syncthreads();
#pragma unroll
    for (int i = 0; i < 4; i++)
#pragma unroll
        for (int j = 0; j < 2; j++)
            wmma::store_matrix_sync(&As[(wm * 64 + i * 16) * SE + wn * 32 + j * 16],
                                    acc[i][j], SE, wmma::mem_row_major);
    __syncthreads();
    for (int i = tid; i < 256 * 64; i += 256) {
        int r = i >> 6, c = i & 63;
        C[(m0 + r) * N + n0 + c] = As[r * SE + c] + bias[n0 + c];
    }
}

// ======== out_proj fused: attention pre-pass + GEMM(K=64) + residual + LN1 ========
__global__ void __launch_bounds__(256)
oproj_attn_ln(const float* __restrict__ qkv, const float* __restrict__ W,
              const float* __restrict__ bias, const float* __restrict__ res,
              const float* __restrict__ g, const float* __restrict__ be,
              float* __restrict__ outp) {
    extern __shared__ float sm[];
    float* As = sm;
    float* Ws = sm + 128 * SE;
    const int tid = threadIdx.x;
    const int warp = tid >> 5;
    const int lane = tid & 31;
    const int wm = warp >> 1, wn = warp & 1;
    const size_t m0 = (size_t)blockIdx.y * 128;

#pragma unroll
    for (int it = 0; it < 2; it++) {
        int idx = it * 256 + tid;
        int row = idx >> 2, h = idx & 3;
        size_t m = m0 + row;
        int b = (m >= (size_t)HWc) ? 1 : 0;
        int n = (int)(m - (size_t)b * HWc);
        const float* qp = qkv + m * 192 + h * 16;
        const float* k0 = qkv + (size_t)n * 192 + 64 + h * 16;
        const float* k1 = qkv + ((size_t)HWc + n) * 192 + 64 + h * 16;
        const float* v0 = qkv + (size_t)n * 192 + 128 + h * 16;
        const float* v1 = qkv + ((size_t)HWc + n) * 192 + 128 + h * 16;
        float s0 = 0.f, s1 = 0.f;
#pragma unroll
        for (int d = 0; d < 16; d++) { float qv = qp[d]; s0 += qv * k0[d]; s1 += qv * k1[d]; }
        s0 *= 0.25f; s1 *= 0.25f;
        float mx = fmaxf(s0, s1);
        float e0 = expf(s0 - mx), e1 = expf(s1 - mx);
        float inv = 1.f / (e0 + e1);
        float p0 = e0 * inv, p1 = e1 * inv;
#pragma unroll
        for (int d = 0; d < 16; d++)
            As[row * SE + h * 16 + d] = to_tf32(p0 * v0[d] + p1 * v1[d]);
    }
#pragma unroll
    for (int i = tid; i < 64 * 16; i += 256) {
        int n = i >> 4, q = i & 15;
        float4 v = *(const float4*)&W[(size_t)n * 64 + q * 4];
        *(float4*)&Ws[n * SE + q * 4] = to_tf32_4(v);
    }
    __syncthreads();

    wmma::fragment<wmma::accumulator, 16, 16, 8, float> acc[2][2];
#pragma unroll
    for (int i = 0; i < 2; i++)
#pragma unroll
        for (int j = 0; j < 2; j++) wmma::fill_fragment(acc[i][j], 0.f);
#pragma unroll
    for (int ks = 0; ks < 8; ks++) {
        wmma::fragment<wmma::matrix_a, 16, 16, 8, wmma::precision::tf32, wmma::row_major> a[2];
        wmma::fragment<wmma::matrix_b, 16, 16, 8, wmma::precision::tf32, wmma::col_major> b[2];
#pragma unroll
        for (int i = 0; i < 2; i++)
            wmma::load_matrix_sync(a[i], &As[(wm * 32 + i * 16) * SE + ks * 8], SE);
#pragma unroll
        for (int j = 0; j < 2; j++)
            wmma::load_matrix_sync(b[j], &Ws[(wn * 32 + j * 16) * SE + ks * 8], SE);
#pragma unroll
        for (int i = 0; i < 2; i++)
#pragma unroll
            for (int j = 0; j < 2; j++)
                wmma::mma_sync(acc[i][j], a[i], b[j], acc[i][j]);
    }
    __syncthreads();
#pragma unroll
    for (int i = 0; i < 2; i++)
#pragma unroll
        for (int j = 0; j < 2; j++)
            wmma::store_matrix_sync(&As[(wm * 32 + i * 16) * SE + wn * 32 + j * 16],
                                    acc[i][j], SE, wmma::mem_row_major);
    __syncthreads();
    for (int r = warp * 16; r < warp * 16 + 16; r++) {
        size_t m = m0 + r;
        float x0 = As[r * SE + lane] + bias[lane] + res[m * 64 + lane];
        float x1 = As[r * SE + 32 + lane] + bias[32 + lane] + res[m * 64 + 32 + lane];
        float s = x0 + x1;
#pragma unroll
        for (int o = 16; o > 0; o >>= 1) s += __shfl_xor_sync(0xffffffffu, s, o);
        float mu = s * (1.f / 64.f);
        float c0 = x0 - mu, c1 = x1 - mu;
        float sq = c0 * c0 + c1 * c1;
#pragma unroll
        for (int o = 16; o > 0; o >>= 1) sq += __shfl_xor_sync(0xffffffffu, sq, o);
        float rs = rsqrtf(sq * (1.f / 64.f) + 1e-5f);
        outp[m * 64 + lane]      = g[lane] * c0 * rs + be[lane];
        outp[m * 64 + 32 + lane] = g[lane + 32] * c1 * rs + be[lane + 32];
    }
}

// ======== small conv (CIN=3 or 1): implicit im2col, K padded to 32, BM=256 ========
template<int CIN>
__global__ void __launch_bounds__(256)
small_conv(const float* __restrict__ src, const float* __restrict__ W,
           const float* __restrict__ bias, float* __restrict__ C, int act) {
    constexpr int K = CIN * 9;
    extern __shared__ float sm[];
    float* As = sm;
    float* Ws = sm + 256 * SA;
    const int tid = threadIdx.x;
    const int warp = tid >> 5;
    const int wm = warp >> 1, wn = warp & 1;
    const size_t m0 = (size_t)blockIdx.y * 256;

#pragma unroll
    for (int u = 0; u < 8; u++) {
        int i = tid + u * 256;
        int row = i >> 3, q = i & 7;
        int m = (int)m0 + row;
        int b = m / HWc, pix = m % HWc;
        int y = pix / Wc, x = pix % Wc;
        float vv[4];
#pragma unroll
        for (int e = 0; e < 4; e++) {
            int k = q * 4 + e;
            float v = 0.f;
            if (k < K) {
                int ci = k / 9, kk = k % 9;
                int py = y + kk / 3 - 1, px = x + kk % 3 - 1;
                if (py >= 0 && py < Hc && px >= 0 && px < Wc)
                    v = src[((size_t)(b * CIN + ci) * HWc) + py * Wc + px];
            }
            vv[e] = to_tf32(v);
        }
        *(float4*)&As[row * SA + q * 4] = make_float4(vv[0], vv[1], vv[2], vv[3]);
    }
#pragma unroll
    for (int u = 0; u < 2; u++) {
        int i = tid + u * 256;
        int n = i >> 3, q = i & 7;
        float vv[4];
#pragma unroll
        for (int e = 0; e < 4; e++) {
            int k = q * 4 + e;
            vv[e] = (k < K) ? to_tf32(W[(size_t)n * K + k]) : 0.f;
        }
        *(float4*)&Ws[n * SA + q * 4] = make_float4(vv[0], vv[1], vv[2], vv[3]);
    }
    __syncthreads();

    wmma::fragment<wmma::accumulator, 16, 16, 8, float> acc[4][2];
#pragma unroll
    for (int i = 0; i < 4; i++)
#pragma unroll
        for (int j = 0; j < 2; j++) wmma::fill_fragment(acc[i][j], 0.f);
#pragma unroll
    for (int ks = 0; ks < 4; ks++) {
        wmma::fragment<wmma::matrix_a, 16, 16, 8, wmma::precision::tf32, wmma::row_major> a[4];
        wmma::fragment<wmma::matrix_b, 16, 16, 8, wmma::precision::tf32, wmma::col_major> b[2];
#pragma unroll
        for (int i = 0; i < 4; i++)
            wmma::load_matrix_sync(a[i], &As[(wm * 64 + i * 16) * SA + ks * 8], SA);
#pragma unroll
        for (int j = 0; j < 2; j++)
            wmma::load_matrix_sync(b[j], &Ws[(wn * 32 + j * 16) * SA + ks * 8], SA);
#pragma unroll
        for (int i = 0; i < 4; i++)
#pragma unroll
            for (int j = 0; j < 2; j++)
                wmma::mma_sync(acc[i][j], a[i], b[j], acc[i][j]);
    }
    __syncthreads();
#pragma unroll
    for (int i = 0; i < 4; i++)
#pragma unroll
        for (int j = 0; j < 2; j++)
            wmma::store_matrix_sync(&sm[(wm * 64 + i * 16) * SE + wn * 32 + j * 16],
                                    acc[i][j], SE, wmma::mem_row_major);
    __syncthreads();
    for (int i = tid; i < 256 * 64; i += 256) {
        int r = i >> 6, c = i & 63;
        float v = sm[r * SE + c] + bias[c];
        if (act == 1) v = fmaxf(v, 0.f);
        C[(m0 + r) * 64 + c] = v;
    }
}

// ================= implicit-im2col conv GEMM, templated BM/BN =================
template<int BMT, int BNT, int WM, int WN>
__global__ void __launch_bounds__(256)
conv_gemm_t(const float* __restrict__ src, int Cin,
            const float* __restrict__ Wr, const float* __restrict__ bias,
            float* __restrict__ C, int N, int act) {
    constexpr int FM = BMT / (WM * 16);
    constexpr int FN = BNT / (WN * 16);
    constexpr int SEB = BNT + 4;
    constexpr int AU = BMT / 32;
    constexpr int BU = (BNT * 8 + 255) / 256;
    extern __shared__ float sm[];
    float* AsB = sm;
    float* BsB = sm + 2 * BMT * SA;

    const int tid = threadIdx.x;
    const int warp = tid >> 5;
    const int wm = warp / WN, wn = warp % WN;
    const size_t m0 = (size_t)blockIdx.y * BMT;
    const int n0 = blockIdx.x * BNT;
    const int K = 9 * Cin;
    const int chunks = K / BK;

    float4 aR[AU], bR[BU];

    auto load_glb = [&](int c) {
        const int k0 = c * BK;
        const int kk = k0 / Cin;
        const int ci0 = k0 % Cin;
        const int ky = kk / 3 - 1, kx = kk % 3 - 1;
#pragma unroll
        for (int u = 0; u < AU; u++) {
            int i = tid + u * 256;
            int row = i >> 3, q = i & 7;
            int m = (int)m0 + row;
            int b = m / HWc, pix = m % HWc;
            int y = pix / Wc, x = pix % Wc;
            int py = y + ky, px = x + kx;
            float4 v = make_float4(0.f, 0.f, 0.f, 0.f);
            if (py >= 0 && py < Hc && px >= 0 && px < Wc)
                v = *(const float4*)&src[((size_t)b * HWc + py * Wc + px) * Cin + ci0 + q * 4];
            aR[u] = v;
        }
#pragma unroll
        for (int u = 0; u < BU; u++) {
            int i = tid + u * 256;
            float4 v = make_float4(0.f, 0.f, 0.f, 0.f);
            if (i < BNT * 8) {
                int n = i >> 3, q = i & 7;
                int gn = n0 + n;
                if (gn < N) v = *(const float4*)&Wr[(size_t)gn * K + k0 + q * 4];
            }
            bR[u] = v;
        }
    };
    auto sts_all = [&](int buf) {
        float* Ab = AsB + buf * BMT * SA;
        float* Bb = BsB + buf * BNT * SA;
#pragma unroll
        for (int u = 0; u < AU; u++) {
            int i = tid + u * 256;
            int row = i >> 3, q = i & 7;
            *(float4*)&Ab[row * SA + q * 4] = to_tf32_4(aR[u]);
        }
#pragma unroll
        for (int u = 0; u < BU; u++) {
            int i = tid + u * 256;
            if (i < BNT * 8) {
                int n = i >> 3, q = i & 7;
                *(float4*)&Bb[n * SA + q * 4] = to_tf32_4(bR[u]);
            }
        }
    };

    wmma::fragment<wmma::accumulator, 16, 16, 8, float> acc[FM][FN];
#pragma unroll
    for (int i = 0; i < FM; i++)
#pragma unroll
        for (int j = 0; j < FN; j++) wmma::fill_fragment(acc[i][j], 0.f);

    load_glb(0); sts_all(0);
    __syncthreads();
    for (int c = 0; c < chunks; c++) {
        const int buf = c & 1;
        if (c + 1 < chunks) load_glb(c + 1);
        float* Ab = AsB + buf * BMT * SA;
        float* Bb = BsB + buf * BNT * SA;
#pragma unroll
        for (int ks = 0; ks < 4; ks++) {
            wmma::fragment<wmma::matrix_a, 16, 16, 8, wmma::precision::tf32, wmma::row_major> a[FM];
            wmma::fragment<wmma::matrix_b, 16, 16, 8, wmma::precision::tf32, wmma::col_major> b[FN];
#pragma unroll
            for (int i = 0; i < FM; i++)
                wmma::load_matrix_sync(a[i], &Ab[((wm * FM + i) * 16) * SA + ks * 8], SA);
#pragma unroll
            for (int j = 0; j < FN; j++)
                wmma::load_matrix_sync(b[j], &Bb[((wn * FN + j) * 16) * SA + ks * 8], SA);
#pragma unroll
            for (int i = 0; i < FM; i++)
#pragma unroll
                for (int j = 0; j < FN; j++)
                    wmma::mma_sync(acc[i][j], a[i], b[j], acc[i][j]);
        }
        if (c + 1 < chunks) sts_all((c + 1) & 1);
        __syncthreads();
    }

#pragma unroll
    for (int i = 0; i < FM; i++)
#pragma unroll
        for (int j = 0; j < FN; j++)
            wmma::store_matrix_sync(&sm[((wm * FM + i) * 16) * SEB + (wn * FN + j) * 16],
                                    acc[i][j], SEB, wmma::mem_row_major);
    __syncthreads();
    for (int i = tid; i < BMT * BNT; i += 256) {
        int r = i / BNT, col = i % BNT;
        int gn = n0 + col;
        if (gn >= N) continue;
        float v = sm[r * SEB + col] + bias[gn];
        if (act == 1) v = fmaxf(v, 0.f);
        else if (act == 2) v = 1.f / (1.f + expf(-v));
        C[(m0 + r) * N + gn] = v;
    }
}

// ===== fused FFN + residual + LN2: BM=256, double-buffered W (proven R11) =====
__global__ void __launch_bounds__(256)
ffn_fused(const float* __restrict__ A, const float* __restrict__ W1,
          const float* __restrict__ B1, const float* __restrict__ W2,
          const float* __restrict__ B2,
          const float* __restrict__ g2, const float* __restrict__ be2,
          float* __restrict__ T2out) {
    extern __shared__ float fsm[];
    float* As  = fsm;
    float* W1s = As + FBM * FSA;
    float* W2s = W1s + 2 * 64 * FSA;
    float* Hs  = W2s + 2 * 64 * SE;
    const int tid = threadIdx.x;
    const int warp = tid >> 5;
    const int lane = tid & 31;
    const int wm = warp >> 1, wn = warp & 1;
    const size_t m0 = (size_t)blockIdx.x * FBM;

    float4 wR[4];
    auto loadW1 = [&](int c) {
#pragma unroll
        for (int u = 0; u < 4; u++) {
            int i = tid + u * 256;
            int n = i >> 4, q = i & 15;
            wR[u] = *(const float4*)&W1[((size_t)c * 64 + n) * 64 + q * 4];
        }
    };
    auto stsW1 = [&](int buf, int c) {
        float* d = W1s + buf * 64 * FSA;
#pragma unroll
        for (int u = 0; u < 4; u++) {
            int i = tid + u * 256;
            int n = i >> 4, q = i & 15;
            *(float4*)&d[n * FSA + q * 4] = to_tf32_4(wR[u]);
        }
        if (tid < 64) {
            float bv = to_tf32(__ldg(&B1[(size_t)c * 64 + tid]));
            *(float4*)&d[tid * FSA + 64] = make_float4(bv, 0.f, 0.f, 0.f);
            *(float4*)&d[tid * FSA + 68] = make_float4(0.f, 0.f, 0.f, 0.f);
            *(float4*)&d[tid * FSA + 72] = make_float4(0.f, 0.f, 0.f, 0.f);
        }
    };
    auto loadW2 = [&](int c) {
#pragma unroll
        for (int u = 0; u < 4; u++) {
            int i = tid + u * 256;
            int o = i >> 4, q = i & 15;
            wR[u] = *(const float4*)&W2[(size_t)o * DFFc + c * 64 + q * 4];
        }
    };
    auto stsW2 = [&](int buf) {
        float* d = W2s + buf * 64 * SE;
#pragma unroll
        for (int u = 0; u < 4; u++) {
            int i = tid + u * 256;
            int o = i >> 4, q = i & 15;
            *(float4*)&d[o * SE + q * 4] = to_tf32_4(wR[u]);
        }
    };

#pragma unroll
    for (int i = tid; i < FBM * 16; i += 256) {
        int row = i >> 4, q = i & 15;
        float4 v = *(const float4*)&A[(m0 + row) * 64 + q * 4];
        *(float4*)&As[row * FSA + q * 4] = to_tf32_4(v);
    }
    for (int row = tid; row < FBM; row += 256) {
        *(float4*)&As[row * FSA + 64] = make_float4(1.f, 0.f, 0.f, 0.f);
        *(float4*)&As[row * FSA + 68] = make_float4(0.f, 0.f, 0.f, 0.f);
        *(float4*)&As[row * FSA + 72] = make_float4(0.f, 0.f, 0.f, 0.f);
    }
    loadW1(0); stsW1(0, 0);
    loadW2(0); stsW2(0);
    __syncthreads();

    wmma::fragment<wmma::accumulator, 16, 16, 8, float> out[4][2];
#pragma unroll
    for (int i = 0; i < 4; i++)
#pragma unroll
        for (int j = 0; j < 2; j++) wmma::fill_fragment(out[i][j], 0.f);

    for (int c = 0; c < 32; c++) {
        const int buf = c & 1;
        if (c + 1 < 32) loadW1(c + 1);
        float* W1b = W1s + buf * 64 * FSA;
        float* W2b = W2s + buf * 64 * SE;

        wmma::fragment<wmma::accumulator, 16, 16, 8, float> hacc[4][2];
#pragma unroll
        for (int i = 0; i < 4; i++)
#pragma unroll
            for (int j = 0; j < 2; j++) wmma::fill_fragment(hacc[i][j], 0.f);
#pragma unroll
        for (int ks = 0; ks < 9; ks++) {
            wmma::fragment<wmma::matrix_a, 16, 16, 8, wmma::precision::tf32, wmma::row_major> a[4];
            wmma::fragment<wmma::matrix_b, 16, 16, 8, wmma::precision::tf32, wmma::col_major> b[2];
#pragma unroll
            for (int i = 0; i < 4; i++)
                wmma::load_matrix_sync(a[i], &As[(wm * 64 + i * 16) * FSA + ks * 8], FSA);
#pragma unroll
            for (int j = 0; j < 2; j++)
                wmma::load_matrix_sync(b[j], &W1b[(wn * 32 + j * 16) * FSA + ks * 8], FSA);
#pragma unroll
            for (int i = 0; i < 4; i++)
#pragma unroll
                for (int j = 0; j < 2; j++)
                    wmma::mma_sync(hacc[i][j], a[i], b[j], hacc[i][j]);
        }
#pragma unroll
        for (int i = 0; i < 4; i++)
#pragma unroll
            for (int j = 0; j < 2; j++) {
#pragma unroll
                for (int e = 0; e < hacc[i][j].num_elements; e++)
                    hacc[i][j].x[e] = to_tf32(fmaxf(hacc[i][j].x[e], 0.f));
                wmma::store_matrix_sync(&Hs[(wm * 64 + i * 16) * SE + wn * 32 + j * 16],
                                        hacc[i][j], SE, wmma::mem_row_major);
            }
        if (c + 1 < 32) stsW1((c + 1) & 1, c + 1);
        __syncthreads();

        if (c + 1 < 32) loadW2(c + 1);
#pragma unroll
        for (int ks = 0; ks < 8; ks++) {
            wmma::fragment<wmma::matrix_a, 16, 16, 8, wmma::precision::tf32, wmma::row_major> a[4];
            wmma::fragment<wmma::matrix_b, 16, 16, 8, wmma::precision::tf32, wmma::col_major> b[2];
#pragma unroll
            for (int i = 0; i < 4; i++)
                wmma::load_matrix_sync(a[i], &Hs[(wm * 64 + i * 16) * SE + ks * 8], SE);
#pragma unroll
            for (int j = 0; j < 2; j++)
                wmma::load_matrix_sync(b[j], &W2b[(wn * 32 + j * 16) * SE + ks * 8], SE);
#pragma unroll
            for (int i = 0; i < 4; i++)
#pragma unroll
                for (int j = 0; j < 2; j++)
                    wmma::mma_sync(out[i][j], a[i], b[j], out[i][j]);
        }
        if (c + 1 < 32) stsW2((c + 1) & 1);
        __syncthreads();
    }

#pragma unroll
    for (int i = 0; i < 4; i++)
#pragma unroll
        for (int j = 0; j < 2; j++)
            wmma::store_matrix_sync(&Hs[(wm * 64 + i * 16) * SE + wn * 32 + j * 16],
                                    out[i][j], SE, wmma::mem_row_major);
    __syncthreads();
    for (int r = warp * 32; r < warp * 32 + 32; r++) {
        size_t m = m0 + r;
        float x0 = Hs[r * SE + lane] + B2[lane] + A[m * 64 + lane];
        float x1 = Hs[r * SE + 32 + lane] + B2[32 + lane] + A[m * 64 + 32 + lane];
        float s = x0 + x1;
#pragma unroll
        for (int o = 16; o > 0; o >>= 1) s += __shfl_xor_sync(0xffffffffu, s, o);
        float mu = s * (1.f / 64.f);
        float c0 = x0 - mu, c1 = x1 - mu;
        float sq = c0 * c0 + c1 * c1;
#pragma unroll
        for (int o = 16; o > 0; o >>= 1) sq += __shfl_xor_sync(0xffffffffu, sq, o);
        float rs = rsqrtf(sq * (1.f / 64.f) + 1e-5f);
        T2out[m * 64 + lane]      = g2[lane] * c0 * rs + be2[lane];
        T2out[m * 64 + 32 + lane] = g2[lane + 32] * c1 * rs + be2[lane + 32];
    }
}

// ---------------- weight reorder ----------------
__global__ void reorder_w(const float* __restrict__ in, float* __restrict__ out,
                          int O, int Cin) {
    int K = Cin * 9;
    int i = blockIdx.x * 256 + threadIdx.x;
    if (i >= O * K) return;
    int o = i / K, k = i % K;
    int kk = k / Cin, ci = k % Cin;
    out[(size_t)o * K + k] = in[(size_t)o * K + ci * 9 + kk];
}

// ======== fused sf2 conv (N=9, K=288) + per-pixel adaptive filter, scalar fp32 ====
// sf1 channel-last [MTOK,32]; w2 original layout [9][32][3][3]; out fus[MTOK]
__global__ void __launch_bounds__(256)
sf2_fuse(const float* __restrict__ sf1, const float* __restrict__ w2,
         const float* __restrict__ b2, const float* __restrict__ xin,
         float* __restrict__ fus) {
    __shared__ float ws[9 * 288];
    for (int i = threadIdx.x; i < 9 * 288; i += 256) ws[i] = w2[i];
    __syncthreads();
    int m = blockIdx.x * 256 + threadIdx.x;
    if (m >= MTOK) return;
    int b = m / HWc, pix = m % HWc;
    int y = pix / Wc, x = pix % Wc;

    float filt[9];
#pragma unroll
    for (int j = 0; j < 9; j++) filt[j] = b2[j];
#pragma unroll
    for (int t = 0; t < 9; t++) {
        int py = y + t / 3 - 1, px = x + t % 3 - 1;
        if (py < 0 || py >= Hc || px < 0 || px >= Wc) continue;
        const float* srow = sf1 + ((size_t)b * HWc + py * Wc + px) * 32;
#pragma unroll
        for (int c4 = 0; c4 < 8; c4++) {
            float4 v = *(const float4*)&srow[c4 * 4];
#pragma unroll
            for (int j = 0; j < 9; j++) {
                const float* wj = ws + j * 288 + (c4 * 4) * 9 + t;
                filt[j] += v.x * wj[0] + v.y * wj[9] + v.z * wj[18] + v.w * wj[27];
            }
        }
    }
    const float* xb = xin + (size_t)b * 3 * HWc;
    float acc = 0.f;
#pragma unroll
    for (int t = 0; t < 9; t++) {
        int py = y + t / 3 - 1, px = x + t % 3 - 1;
        if (py < 0 || py >= Hc || px < 0 || px >= Wc) continue;
        int p = py * Wc + px;
        float s = xb[p] + xb[HWc + p] + xb[2 * HWc + p];
        acc += filt[t] * s;
    }
    fus[m] = acc;
}

// ======== dec2 conv (N=1, K=576) + sigmoid, scalar fp32 ========
// d1 channel-last [MTOK,64]; w original layout [1][64][3][3] -> w[ci*9 + t]
__global__ void __launch_bounds__(256)
dec2_k(const float* __restrict__ d1, const float* __restrict__ w,
       const float* __restrict__ b, float* __restrict__ outp) {
    __shared__ float ws[576];
    for (int i = threadIdx.x; i < 576; i += 256) ws[i] = w[i];
    __syncthreads();
    int m = blockIdx.x * 256 + threadIdx.x;
    if (m >= MTOK) return;
    int bb = m / HWc, pix = m % HWc;
    int y = pix / Wc, x = pix % Wc;
    float acc = b[0];
#pragma unroll
    for (int t = 0; t < 9; t++) {
        int py = y + t / 3 - 1, px = x + t % 3 - 1;
        if (py < 0 || py >= Hc || px < 0 || px >= Wc) continue;
        const float* row = d1 + ((size_t)bb * HWc + py * Wc + px) * 64;
#pragma unroll
        for (int c4 = 0; c4 < 16; c4++) {
            float4 v = *(const float4*)&row[c4 * 4];
            const float* wp = ws + (c4 * 4) * 9 + t;
            acc += v.x * wp[0] + v.y * wp[9] + v.z * wp[18] + v.w * wp[27];
        }
    }
    outp[m] = 1.f / (1.f + expf(-acc));
}

template<int BMT, int BNT, int WM, int WN>
static void run_conv_t(const float* src, int Cin, const float* Wr, const float* b,
                       float* C, int N, int act) {
    constexpr int SM1 = (2 * BMT * SA + 2 * BNT * SA) * 4;
    constexpr int SM2 = (BMT * (BNT + 4)) * 4;
    constexpr int SM = SM1 > SM2 ? SM1 : SM2;
    cudaFuncSetAttribute(conv_gemm_t<BMT, BNT, WM, WN>,
                         cudaFuncAttributeMaxDynamicSharedMemorySize, SM);
    dim3 g((N + BNT - 1) / BNT, MTOK / BMT);
    conv_gemm_t<BMT, BNT, WM, WN><<<g, 256, SM>>>(src, Cin, Wr, b, C, N, act);
}

extern "C" void kernel_launch(void* const* d_in, const int* in_sizes, int n_in,
                              void* d_out, int out_size) {
    const float* x        = (const float*)d_in[0];
    const float* enc_w1   = (const float*)d_in[1];
    const float* enc_b1   = (const float*)d_in[2];
    const float* enc_w2   = (const float*)d_in[3];
    const float* enc_b2   = (const float*)d_in[4];
    const float* in_pw    = (const float*)d_in[5];
    const float* in_pb    = (const float*)d_in[6];
    const float* out_pw   = (const float*)d_in[7];
    const float* out_pb   = (const float*)d_in[8];
    const float* ln1_g    = (const float*)d_in[9];
    const float* ln1_b    = (const float*)d_in[10];
    const float* ffn_w1   = (const float*)d_in[11];
    const float* ffn_b1   = (const float*)d_in[12];
    const float* ffn_w2   = (const float*)d_in[13];
    const float* ffn_b2   = (const float*)d_in[14];
    const float* ln2_g    = (const float*)d_in[15];
    const float* ln2_b    = (const float*)d_in[16];
    const float* sf_w1    = (const float*)d_in[17];
    const float* sf_b1    = (const float*)d_in[18];
    const float* sf_w2    = (const float*)d_in[19];
    const float* sf_b2    = (const float*)d_in[20];
    const float* dec_w1   = (const float*)d_in[21];
    const float* dec_b1   = (const float*)d_in[22];
    const float* dec_w2   = (const float*)d_in[23];
    const float* dec_b2   = (const float*)d_in[24];
    float* out = (float*)d_out;

    float *bufA, *t, *qkv, *t1, *t2, *sf1, *fus, *d1, *wr;
    cudaGetSymbolAddress((void**)&bufA, g_bufA);
    cudaGetSymbolAddress((void**)&t,    g_t);
    cudaGetSymbolAddress((void**)&qkv,  g_qkv);
    cudaGetSymbolAddress((void**)&t1,   g_t1);
    cudaGetSymbolAddress((void**)&t2,   g_t2);
    cudaGetSymbolAddress((void**)&sf1,  g_sf1);
    cudaGetSymbolAddress((void**)&fus,  g_fus);
    cudaGetSymbolAddress((void**)&d1,   g_d1);
    cudaGetSymbolAddress((void**)&wr,   g_wr);

    float* wr_enc2 = wr;
    float* wr_sf1  = wr_enc2 + 64 * 576;

    cudaFuncSetAttribute(ffn_fused, cudaFuncAttributeMaxDynamicSharedMemorySize, FFN_SMEM);
    cudaFuncSetAttribute(qkv_gemm, cudaFuncAttributeMaxDynamicSharedMemorySize, QKV_SMEM);
    cudaFuncSetAttribute(oproj_attn_ln, cudaFuncAttributeMaxDynamicSharedMemorySize, OPROJ_SMEM);
    cudaFuncSetAttribute(small_conv<3>, cudaFuncAttributeMaxDynamicSharedMemorySize, SCONV_SMEM);
    cudaFuncSetAttribute(small_conv<1>, cudaFuncAttributeMaxDynamicSharedMemorySize, SCONV_SMEM);

    const int M = MTOK;
    auto blocks = [](long total, int thr) { return (int)((total + thr - 1) / thr); };

    reorder_w<<<blocks(64 * 576, 256), 256>>>(enc_w2, wr_enc2, 64, 64);
    reorder_w<<<blocks(32 * 576, 256), 256>>>(sf_w1, wr_sf1, 32, 64);

    // ---- encoder ----
    { dim3 g(1, M / 256); small_conv<3><<<g, 256, SCONV_SMEM>>>(x, enc_w1, enc_b1, bufA, 1); }
    run_conv_t<256, 64, 4, 2>(bufA, 64, wr_enc2, enc_b2, t, 64, 1);

    // ---- transformer ----
    { dim3 g(3, M / 256); qkv_gemm<<<g, 256, QKV_SMEM>>>(t, in_pw, in_pb, qkv, 192); }
    { dim3 g(1, M / 128); oproj_attn_ln<<<g, 256, OPROJ_SMEM>>>(qkv, out_pw, out_pb, t,
                                                                ln1_g, ln1_b, t1); }
    ffn_fused<<<M / FBM, 256, FFN_SMEM>>>(t1, ffn_w1, ffn_b1, ffn_w2, ffn_b2,
                                          ln2_g, ln2_b, t2);

    // ---- spatial filter branch (sf2 + per-pixel filter fused, scalar) ----
    run_conv_t<256, 32, 4, 2>(t2, 64, wr_sf1, sf_b1, sf1, 32, 0);
    sf2_fuse<<<blocks((long)M, 256), 256>>>(sf1, sf_w2, sf_b2, x, fus);

    // ---- decoder ----
    { dim3 g(1, M / 256); small_conv<1><<<g, 256, SCONV_SMEM>>>(fus, dec_w1, dec_b1, d1, 1); }
    dec2_k<<<blocks((long)M, 256), 256>>>(d1, dec_w2, dec_b2, out);
}

// round 14
// speedup vs baseline: 1.0054x; 1.0054x over previous
#include <cuda_runtime.h>
#include <mma.h>
#include <cstdint>
#include <math.h>

using namespace nvcuda;

#define Hc   224
#define Wc   224
#define HWc  (Hc * Wc)
#define Bc   2
#define MTOK (Bc * HWc)      // 100352
#define Ec   64
#define NHc  4
#define DHc  16
#define DFFc 2048

// ---------------- scratch ----------------
__device__ float g_bufA[MTOK * 64];
__device__ float g_t   [MTOK * 64];
__device__ float g_qkv [MTOK * 192];
__device__ float g_t1  [MTOK * 64];
__device__ float g_t2  [MTOK * 64];
__device__ float g_sf1 [MTOK * 32];
__device__ float g_fus [MTOK];
__device__ float g_d1  [MTOK * 64];
__device__ float g_wr  [64 * 576 + 32 * 576];

__device__ __forceinline__ float to_tf32(float x) {
    uint32_t r;
    asm("cvt.rna.tf32.f32 %0, %1;" : "=r"(r) : "f"(x));
    return __uint_as_float(r);
}
__device__ __forceinline__ float4 to_tf32_4(float4 v) {
    return make_float4(to_tf32(v.x), to_tf32(v.y), to_tf32(v.z), to_tf32(v.w));
}

#define SA 36
#define SE 68
#define FSA 76
#define BK 32
#define FBM 256
#define FFN_SMEM ((FBM * FSA + 2 * 64 * FSA + 2 * 64 * SE + FBM * SE) * 4)
#define QKV_SMEM ((256 * SE + 64 * SE) * 4)
#define OPROJ_SMEM ((128 * SE + 64 * SE) * 4)
#define SCONV_SMEM ((256 * SE) * 4)

// ============ qkv GEMM: C[M,192] = A[M,64] @ W[192,64]^T + bias, BM=256 ============
__global__ void __launch_bounds__(256)
qkv_gemm(const float* __restrict__ A, const float* __restrict__ W,
         const float* __restrict__ bias, float* __restrict__ C, int N) {
    extern __shared__ float sm[];
    float* As = sm;
    float* Ws = sm + 256 * SE;
    const int tid = threadIdx.x;
    const int warp = tid >> 5;
    const int wm = warp >> 1, wn = warp & 1;
    const size_t m0 = (size_t)blockIdx.y * 256;
    const int n0 = blockIdx.x * 64;

#pragma unroll
    for (int i = tid; i < 256 * 16; i += 256) {
        int row = i >> 4, q = i & 15;
        float4 v = *(const float4*)&A[(m0 + row) * 64 + q * 4];
        *(float4*)&As[row * SE + q * 4] = to_tf32_4(v);
    }
#pragma unroll
    for (int i = tid; i < 64 * 16; i += 256) {
        int n = i >> 4, q = i & 15;
        float4 v = *(const float4*)&W[(size_t)(n0 + n) * 64 + q * 4];
        *(float4*)&Ws[n * SE + q * 4] = to_tf32_4(v);
    }
    __syncthreads();

    wmma::fragment<wmma::accumulator, 16, 16, 8, float> acc[4][2];
#pragma unroll
    for (int i = 0; i < 4; i++)
#pragma unroll
        for (int j = 0; j < 2; j++) wmma::fill_fragment(acc[i][j], 0.f);
#pragma unroll
    for (int ks = 0; ks < 8; ks++) {
        wmma::fragment<wmma::matrix_a, 16, 16, 8, wmma::precision::tf32, wmma::row_major> a[4];
        wmma::fragment<wmma::matrix_b, 16, 16, 8, wmma::precision::tf32, wmma::col_major> b[2];
#pragma unroll
        for (int i = 0; i < 4; i++)
            wmma::load_matrix_sync(a[i], &As[(wm * 64 + i * 16) * SE + ks * 8], SE);
#pragma unroll
        for (int j = 0; j < 2; j++)
            wmma::load_matrix_sync(b[j], &Ws[(wn * 32 + j * 16) * SE + ks * 8], SE);
#pragma unroll
        for (int i = 0; i < 4; i++)
#pragma unroll
            for (int j = 0; j < 2; j++)
                wmma::mma_sync(acc[i][j], a[i], b[j], acc[i][j]);
    }
    __syncthreads();
#pragma unroll
    for (int i = 0; i < 4; i++)
#pragma unroll
        for (int j = 0; j < 2; j++)
            wmma::store_matrix_sync(&As[(wm * 64 + i * 16) * SE + wn * 32 + j * 16],
                                    acc[i][j], SE, wmma::mem_row_major);
    __syncthreads();
    for (int i = tid; i < 256 * 64; i += 256) {
        int r = i >> 6, c = i & 63;
        C[(m0 + r) * N + n0 + c] = As[r * SE + c] + bias[n0 + c];
    }
}

// ======== out_proj fused: attention pre-pass + GEMM(K=64) + residual + LN1 ========
__global__ void __launch_bounds__(256)
oproj_attn_ln(const float* __restrict__ qkv, const float* __restrict__ W,
              const float* __restrict__ bias, const float* __restrict__ res,
              const float* __restrict__ g, const float* __restrict__ be,
              float* __restrict__ outp) {
    extern __shared__ float sm[];
    float* As = sm;
    float* Ws = sm + 128 * SE;
    const int tid = threadIdx.x;
    const int warp = tid >> 5;
    const int lane = tid & 31;
    const int wm = warp >> 1, wn = warp & 1;
    const size_t m0 = (size_t)blockIdx.y * 128;

#pragma unroll
    for (int it = 0; it < 2; it++) {
        int idx = it * 256 + tid;
        int row = idx >> 2, h = idx & 3;
        size_t m = m0 + row;
        int b = (m >= (size_t)HWc) ? 1 : 0;
        int n = (int)(m - (size_t)b * HWc);
        const float* qp = qkv + m * 192 + h * 16;
        const float* k0 = qkv + (size_t)n * 192 + 64 + h * 16;
        const float* k1 = qkv + ((size_t)HWc + n) * 192 + 64 + h * 16;
        const float* v0 = qkv + (size_t)n * 192 + 128 + h * 16;
        const float* v1 = qkv + ((size_t)HWc + n) * 192 + 128 + h * 16;
        float s0 = 0.f, s1 = 0.f;
#pragma unroll
        for (int d = 0; d < 16; d++) { float qv = qp[d]; s0 += qv * k0[d]; s1 += qv * k1[d]; }
        s0 *= 0.25f; s1 *= 0.25f;
        float mx = fmaxf(s0, s1);
        float e0 = expf(s0 - mx), e1 = expf(s1 - mx);
        float inv = 1.f / (e0 + e1);
        float p0 = e0 * inv, p1 = e1 * inv;
#pragma unroll
        for (int d = 0; d < 16; d++)
            As[row * SE + h * 16 + d] = to_tf32(p0 * v0[d] + p1 * v1[d]);
    }
#pragma unroll
    for (int i = tid; i < 64 * 16; i += 256) {
        int n = i >> 4, q = i & 15;
        float4 v = *(const float4*)&W[(size_t)n * 64 + q * 4];
        *(float4*)&Ws[n * SE + q * 4] = to_tf32_4(v);
    }
    __syncthreads();

    wmma::fragment<wmma::accumulator, 16, 16, 8, float> acc[2][2];
#pragma unroll
    for (int i = 0; i < 2; i++)
#pragma unroll
        for (int j = 0; j < 2; j++) wmma::fill_fragment(acc[i][j], 0.f);
#pragma unroll
    for (int ks = 0; ks < 8; ks++) {
        wmma::fragment<wmma::matrix_a, 16, 16, 8, wmma::precision::tf32, wmma::row_major> a[2];
        wmma::fragment<wmma::matrix_b, 16, 16, 8, wmma::precision::tf32, wmma::col_major> b[2];
#pragma unroll
        for (int i = 0; i < 2; i++)
            wmma::load_matrix_sync(a[i], &As[(wm * 32 + i * 16) * SE + ks * 8], SE);
#pragma unroll
        for (int j = 0; j < 2; j++)
            wmma::load_matrix_sync(b[j], &Ws[(wn * 32 + j * 16) * SE + ks * 8], SE);
#pragma unroll
        for (int i = 0; i < 2; i++)
#pragma unroll
            for (int j = 0; j < 2; j++)
                wmma::mma_sync(acc[i][j], a[i], b[j], acc[i][j]);
    }
    __syncthreads();
#pragma unroll
    for (int i = 0; i < 2; i++)
#pragma unroll
        for (int j = 0; j < 2; j++)
            wmma::store_matrix_sync(&As[(wm * 32 + i * 16) * SE + wn * 32 + j * 16],
                                    acc[i][j], SE, wmma::mem_row_major);
    __syncthreads();
    for (int r = warp * 16; r < warp * 16 + 16; r++) {
        size_t m = m0 + r;
        float x0 = As[r * SE + lane] + bias[lane] + res[m * 64 + lane];
        float x1 = As[r * SE + 32 + lane] + bias[32 + lane] + res[m * 64 + 32 + lane];
        float s = x0 + x1;
#pragma unroll
        for (int o = 16; o > 0; o >>= 1) s += __shfl_xor_sync(0xffffffffu, s, o);
        float mu = s * (1.f / 64.f);
        float c0 = x0 - mu, c1 = x1 - mu;
        float sq = c0 * c0 + c1 * c1;
#pragma unroll
        for (int o = 16; o > 0; o >>= 1) sq += __shfl_xor_sync(0xffffffffu, sq, o);
        float rs = rsqrtf(sq * (1.f / 64.f) + 1e-5f);
        outp[m * 64 + lane]      = g[lane] * c0 * rs + be[lane];
        outp[m * 64 + 32 + lane] = g[lane + 32] * c1 * rs + be[lane + 32];
    }
}

// ======== small conv (CIN=3 or 1): implicit im2col, K padded to 32, BM=256 ========
template<int CIN>
__global__ void __launch_bounds__(256)
small_conv(const float* __restrict__ src, const float* __restrict__ W,
           const float* __restrict__ bias, float* __restrict__ C, int act) {
    constexpr int K = CIN * 9;
    extern __shared__ float sm[];
    float* As = sm;
    float* Ws = sm + 256 * SA;
    const int tid = threadIdx.x;
    const int warp = tid >> 5;
    const int wm = warp >> 1, wn = warp & 1;
    const size_t m0 = (size_t)blockIdx.y * 256;

#pragma unroll
    for (int u = 0; u < 8; u++) {
        int i = tid + u * 256;
        int row = i >> 3, q = i & 7;
        int m = (int)m0 + row;
        int b = m / HWc, pix = m % HWc;
        int y = pix / Wc, x = pix % Wc;
        float vv[4];
#pragma unroll
        for (int e = 0; e < 4; e++) {
            int k = q * 4 + e;
            float v = 0.f;
            if (k < K) {
                int ci = k / 9, kk = k % 9;
                int py = y + kk / 3 - 1, px = x + kk % 3 - 1;
                if (py >= 0 && py < Hc && px >= 0 && px < Wc)
                    v = src[((size_t)(b * CIN + ci) * HWc) + py * Wc + px];
            }
            vv[e] = to_tf32(v);
        }
        *(float4*)&As[row * SA + q * 4] = make_float4(vv[0], vv[1], vv[2], vv[3]);
    }
#pragma unroll
    for (int u = 0; u < 2; u++) {
        int i = tid + u * 256;
        int n = i >> 3, q = i & 7;
        float vv[4];
#pragma unroll
        for (int e = 0; e < 4; e++) {
            int k = q * 4 + e;
            vv[e] = (k < K) ? to_tf32(W[(size_t)n * K + k]) : 0.f;
        }
        *(float4*)&Ws[n * SA + q * 4] = make_float4(vv[0], vv[1], vv[2], vv[3]);
    }
    __syncthreads();

    wmma::fragment<wmma::accumulator, 16, 16, 8, float> acc[4][2];
#pragma unroll
    for (int i = 0; i < 4; i++)
#pragma unroll
        for (int j = 0; j < 2; j++) wmma::fill_fragment(acc[i][j], 0.f);
#pragma unroll
    for (int ks = 0; ks < 4; ks++) {
        wmma::fragment<wmma::matrix_a, 16, 16, 8, wmma::precision::tf32, wmma::row_major> a[4];
        wmma::fragment<wmma::matrix_b, 16, 16, 8, wmma::precision::tf32, wmma::col_major> b[2];
#pragma unroll
        for (int i = 0; i < 4; i++)
            wmma::load_matrix_sync(a[i], &As[(wm * 64 + i * 16) * SA + ks * 8], SA);
#pragma unroll
        for (int j = 0; j < 2; j++)
            wmma::load_matrix_sync(b[j], &Ws[(wn * 32 + j * 16) * SA + ks * 8], SA);
#pragma unroll
        for (int i = 0; i < 4; i++)
#pragma unroll
            for (int j = 0; j < 2; j++)
                wmma::mma_sync(acc[i][j], a[i], b[j], acc[i][j]);
    }
    __syncthreads();
#pragma unroll
    for (int i = 0; i < 4; i++)
#pragma unroll
        for (int j = 0; j < 2; j++)
            wmma::store_matrix_sync(&sm[(wm * 64 + i * 16) * SE + wn * 32 + j * 16],
                                    acc[i][j], SE, wmma::mem_row_major);
    __syncthreads();
    for (int i = tid; i < 256 * 64; i += 256) {
        int r = i >> 6, c = i & 63;
        float v = sm[r * SE + c] + bias[c];
        if (act == 1) v = fmaxf(v, 0.f);
        C[(m0 + r) * 64 + c] = v;
    }
}

// ====== implicit-im2col conv GEMM, 512 threads, BM=256, hoisted index math ======
// WMg x WNg warp grid (16 warps). FM = 256/(WMg*16), FN = BNT/(WNg*16).
template<int BNT, int WMg, int WNg>
__global__ void __launch_bounds__(512)
conv_gemm512(const float* __restrict__ src, int Cin,
             const float* __restrict__ Wr, const float* __restrict__ bias,
             float* __restrict__ C, int N, int act) {
    constexpr int FM = 256 / (WMg * 16);
    constexpr int FN = BNT / (WNg * 16);
    constexpr int SEB = BNT + 4;
    extern __shared__ float sm[];
    float* AsB = sm;
    float* BsB = sm + 2 * 256 * SA;

    const int tid = threadIdx.x;
    const int warp = tid >> 5;
    const int wm = warp / WNg, wn = warp % WNg;
    const size_t m0 = (size_t)blockIdx.y * 256;
    const int n0 = blockIdx.x * BNT;
    const int K = 9 * Cin;
    const int chunks = K / BK;

    // hoisted per-thread row info (4 rows per thread)
    int baseOff[4];   // element offset of (b,y,x) row start + q*4
    int pyx[4];       // (y<<16) | x
#pragma unroll
    for (int u = 0; u < 4; u++) {
        int i = tid + u * 512;
        int row = i >> 3, q = i & 7;
        int m = (int)m0 + row;
        int b = m / HWc, pix = m % HWc;
        int y = pix / Wc, x = pix % Wc;
        baseOff[u] = (b * HWc + y * Wc + x) * Cin + q * 4;
        pyx[u] = (y << 16) | x;
    }

    float4 aR[4], bR;
    auto load_glb = [&](int c) {
        const int k0 = c * BK;
        const int kk = k0 / Cin;
        const int ci0 = k0 % Cin;
        const int ky = kk / 3 - 1, kx = kk % 3 - 1;
        const int kd = (ky * Wc + kx) * Cin + ci0;
#pragma unroll
        for (int u = 0; u < 4; u++) {
            int y = pyx[u] >> 16, x = pyx[u] & 0xffff;
            int py = y + ky, px = x + kx;
            float4 v = make_float4(0.f, 0.f, 0.f, 0.f);
            if (py >= 0 && py < Hc && px >= 0 && px < Wc)
                v = *(const float4*)&src[baseOff[u] + kd];
            aR[u] = v;
        }
        {
            float4 v = make_float4(0.f, 0.f, 0.f, 0.f);
            if (tid < BNT * 8) {
                int n = tid >> 3, q = tid & 7;
                int gn = n0 + n;
                if (gn < N) v = *(const float4*)&Wr[(size_t)gn * K + k0 + q * 4];
            }
            bR = v;
        }
    };
    auto sts_all = [&](int buf) {
        float* Ab = AsB + buf * 256 * SA;
        float* Bb = BsB + buf * BNT * SA;
#pragma unroll
        for (int u = 0; u < 4; u++) {
            int i = tid + u * 512;
            int row = i >> 3, q = i & 7;
            *(float4*)&Ab[row * SA + q * 4] = to_tf32_4(aR[u]);
        }
        if (tid < BNT * 8) {
            int n = tid >> 3, q = tid & 7;
            *(float4*)&Bb[n * SA + q * 4] = to_tf32_4(bR);
        }
    };

    wmma::fragment<wmma::accumulator, 16, 16, 8, float> acc[FM][FN];
#pragma unroll
    for (int i = 0; i < FM; i++)
#pragma unroll
        for (int j = 0; j < FN; j++) wmma::fill_fragment(acc[i][j], 0.f);

    load_glb(0); sts_all(0);
    __syncthreads();
    for (int c = 0; c < chunks; c++) {
        const int buf = c & 1;
        if (c + 1 < chunks) load_glb(c + 1);
        float* Ab = AsB + buf * 256 * SA;
        float* Bb = BsB + buf * BNT * SA;
#pragma unroll
        for (int ks = 0; ks < 4; ks++) {
            wmma::fragment<wmma::matrix_a, 16, 16, 8, wmma::precision::tf32, wmma::row_major> a[FM];
            wmma::fragment<wmma::matrix_b, 16, 16, 8, wmma::precision::tf32, wmma::col_major> b[FN];
#pragma unroll
            for (int i = 0; i < FM; i++)
                wmma::load_matrix_sync(a[i], &Ab[((wm * FM + i) * 16) * SA + ks * 8], SA);
#pragma unroll
            for (int j = 0; j < FN; j++)
                wmma::load_matrix_sync(b[j], &Bb[((wn * FN + j) * 16) * SA + ks * 8], SA);
#pragma unroll
            for (int i = 0; i < FM; i++)
#pragma unroll
                for (int j = 0; j < FN; j++)
                    wmma::mma_sync(acc[i][j], a[i], b[j], acc[i][j]);
        }
        if (c + 1 < chunks) sts_all((c + 1) & 1);
        __syncthreads();
    }

#pragma unroll
    for (int i = 0; i < FM; i++)
#pragma unroll
        for (int j = 0; j < FN; j++)
            wmma::store_matrix_sync(&sm[((wm * FM + i) * 16) * SEB + (wn * FN + j) * 16],
                                    acc[i][j], SEB, wmma::mem_row_major);
    __syncthreads();
    for (int i = tid; i < 256 * BNT; i += 512) {
        int r = i / BNT, col = i % BNT;
        int gn = n0 + col;
        if (gn >= N) continue;
        float v = sm[r * SEB + col] + bias[gn];
        if (act == 1) v = fmaxf(v, 0.f);
        C[(m0 + r) * N + gn] = v;
    }
}

// ===== fused FFN + residual + LN2: BM=256, double-buffered W (proven R11) =====
__global__ void __launch_bounds__(256)
ffn_fused(const float* __restrict__ A, const float* __restrict__ W1,
          const float* __restrict__ B1, const float* __restrict__ W2,
          const float* __restrict__ B2,
          const float* __restrict__ g2, const float* __restrict__ be2,
          float* __restrict__ T2out) {
    extern __shared__ float fsm[];
    float* As  = fsm;
    float* W1s = As + FBM * FSA;
    float* W2s = W1s + 2 * 64 * FSA;
    float* Hs  = W2s + 2 * 64 * SE;
    const int tid = threadIdx.x;
    const int warp = tid >> 5;
    const int lane = tid & 31;
    const int wm = warp >> 1, wn = warp & 1;
    const size_t m0 = (size_t)blockIdx.x * FBM;

    float4 wR[4];
    auto loadW1 = [&](int c) {
#pragma unroll
        for (int u = 0; u < 4; u++) {
            int i = tid + u * 256;
            int n = i >> 4, q = i & 15;
            wR[u] = *(const float4*)&W1[((size_t)c * 64 + n) * 64 + q * 4];
        }
    };
    auto stsW1 = [&](int buf, int c) {
        float* d = W1s + buf * 64 * FSA;
#pragma unroll
        for (int u = 0; u < 4; u++) {
            int i = tid + u * 256;
            int n = i >> 4, q = i & 15;
            *(float4*)&d[n * FSA + q * 4] = to_tf32_4(wR[u]);
        }
        if (tid < 64) {
            float bv = to_tf32(__ldg(&B1[(size_t)c * 64 + tid]));
            *(float4*)&d[tid * FSA + 64] = make_float4(bv, 0.f, 0.f, 0.f);
            *(float4*)&d[tid * FSA + 68] = make_float4(0.f, 0.f, 0.f, 0.f);
            *(float4*)&d[tid * FSA + 72] = make_float4(0.f, 0.f, 0.f, 0.f);
        }
    };
    auto loadW2 = [&](int c) {
#pragma unroll
        for (int u = 0; u < 4; u++) {
            int i = tid + u * 256;
            int o = i >> 4, q = i & 15;
            wR[u] = *(const float4*)&W2[(size_t)o * DFFc + c * 64 + q * 4];
        }
    };
    auto stsW2 = [&](int buf) {
        float* d = W2s + buf * 64 * SE;
#pragma unroll
        for (int u = 0; u < 4; u++) {
            int i = tid + u * 256;
            int o = i >> 4, q = i & 15;
            *(float4*)&d[o * SE + q * 4] = to_tf32_4(wR[u]);
        }
    };

#pragma unroll
    for (int i = tid; i < FBM * 16; i += 256) {
        int row = i >> 4, q = i & 15;
        float4 v = *(const float4*)&A[(m0 + row) * 64 + q * 4];
        *(float4*)&As[row * FSA + q * 4] = to_tf32_4(v);
    }
    for (int row = tid; row < FBM; row += 256) {
        *(float4*)&As[row * FSA + 64] = make_float4(1.f, 0.f, 0.f, 0.f);
        *(float4*)&As[row * FSA + 68] = make_float4(0.f, 0.f, 0.f, 0.f);
        *(float4*)&As[row * FSA + 72] = make_float4(0.f, 0.f, 0.f, 0.f);
    }
    loadW1(0); stsW1(0, 0);
    loadW2(0); stsW2(0);
    __syncthreads();

    wmma::fragment<wmma::accumulator, 16, 16, 8, float> out[4][2];
#pragma unroll
    for (int i = 0; i < 4; i++)
#pragma unroll
        for (int j = 0; j < 2; j++) wmma::fill_fragment(out[i][j], 0.f);

    for (int c = 0; c < 32; c++) {
        const int buf = c & 1;
        if (c + 1 < 32) loadW1(c + 1);
        float* W1b = W1s + buf * 64 * FSA;
        float* W2b = W2s + buf * 64 * SE;

        wmma::fragment<wmma::accumulator, 16, 16, 8, float> hacc[4][2];
#pragma unroll
        for (int i = 0; i < 4; i++)
#pragma unroll
            for (int j = 0; j < 2; j++) wmma::fill_fragment(hacc[i][j], 0.f);
#pragma unroll
        for (int ks = 0; ks < 9; ks++) {
            wmma::fragment<wmma::matrix_a, 16, 16, 8, wmma::precision::tf32, wmma::row_major> a[4];
            wmma::fragment<wmma::matrix_b, 16, 16, 8, wmma::precision::tf32, wmma::col_major> b[2];
#pragma unroll
            for (int i = 0; i < 4; i++)
                wmma::load_matrix_sync(a[i], &As[(wm * 64 + i * 16) * FSA + ks * 8], FSA);
#pragma unroll
            for (int j = 0; j < 2; j++)
                wmma::load_matrix_sync(b[j], &W1b[(wn * 32 + j * 16) * FSA + ks * 8], FSA);
#pragma unroll
            for (int i = 0; i < 4; i++)
#pragma unroll
                for (int j = 0; j < 2; j++)
                    wmma::mma_sync(hacc[i][j], a[i], b[j], hacc[i][j]);
        }
#pragma unroll
        for (int i = 0; i < 4; i++)
#pragma unroll
            for (int j = 0; j < 2; j++) {
#pragma unroll
                for (int e = 0; e < hacc[i][j].num_elements; e++)
                    hacc[i][j].x[e] = to_tf32(fmaxf(hacc[i][j].x[e], 0.f));
                wmma::store_matrix_sync(&Hs[(wm * 64 + i * 16) * SE + wn * 32 + j * 16],
                                        hacc[i][j], SE, wmma::mem_row_major);
            }
        if (c + 1 < 32) stsW1((c + 1) & 1, c + 1);
        __syncthreads();

        if (c + 1 < 32) loadW2(c + 1);
#pragma unroll
        for (int ks = 0; ks < 8; ks++) {
            wmma::fragment<wmma::matrix_a, 16, 16, 8, wmma::precision::tf32, wmma::row_major> a[4];
            wmma::fragment<wmma::matrix_b, 16, 16, 8, wmma::precision::tf32, wmma::col_major> b[2];
#pragma unroll
            for (int i = 0; i < 4; i++)
                wmma::load_matrix_sync(a[i], &Hs[(wm * 64 + i * 16) * SE + ks * 8], SE);
#pragma unroll
            for (int j = 0; j < 2; j++)
                wmma::load_matrix_sync(b[j], &W2b[(wn * 32 + j * 16) * SE + ks * 8], SE);
#pragma unroll
            for (int i = 0; i < 4; i++)
#pragma unroll
                for (int j = 0; j < 2; j++)
                    wmma::mma_sync(out[i][j], a[i], b[j], out[i][j]);
        }
        if (c + 1 < 32) stsW2((c + 1) & 1);
        __syncthreads();
    }

#pragma unroll
    for (int i = 0; i < 4; i++)
#pragma unroll
        for (int j = 0; j < 2; j++)
            wmma::store_matrix_sync(&Hs[(wm * 64 + i * 16) * SE + wn * 32 + j * 16],
                                    out[i][j], SE, wmma::mem_row_major);
    __syncthreads();
    for (int r = warp * 32; r < warp * 32 + 32; r++) {
        size_t m = m0 + r;
        float x0 = Hs[r * SE + lane] + B2[lane] + A[m * 64 + lane];
        float x1 = Hs[r * SE + 32 + lane] + B2[32 + lane] + A[m * 64 + 32 + lane];
        float s = x0 + x1;
#pragma unroll
        for (int o = 16; o > 0; o >>= 1) s += __shfl_xor_sync(0xffffffffu, s, o);
        float mu = s * (1.f / 64.f);
        float c0 = x0 - mu, c1 = x1 - mu;
        float sq = c0 * c0 + c1 * c1;
#pragma unroll
        for (int o = 16; o > 0; o >>= 1) sq += __shfl_xor_sync(0xffffffffu, sq, o);
        float rs = rsqrtf(sq * (1.f / 64.f) + 1e-5f);
        T2out[m * 64 + lane]      = g2[lane] * c0 * rs + be2[lane];
        T2out[m * 64 + 32 + lane] = g2[lane + 32] * c1 * rs + be2[lane + 32];
    }
}

// ---------------- weight reorder ----------------
__global__ void reorder_w(const float* __restrict__ in, float* __restrict__ out,
                          int O, int Cin) {
    int K = Cin * 9;
    int i = blockIdx.x * 256 + threadIdx.x;
    if (i >= O * K) return;
    int o = i / K, k = i % K;
    int kk = k / Cin, ci = k % Cin;
    out[(size_t)o * K + k] = in[(size_t)o * K + ci * 9 + kk];
}

// ======== fused sf2 conv (N=9, K=288) + per-pixel adaptive filter, scalar fp32 ====
__global__ void __launch_bounds__(256)
sf2_fuse(const float* __restrict__ sf1, const float* __restrict__ w2,
         const float* __restrict__ b2, const float* __restrict__ xin,
         float* __restrict__ fus) {
    __shared__ float ws[9 * 288];
    for (int i = threadIdx.x; i < 9 * 288; i += 256) ws[i] = w2[i];
    __syncthreads();
    int m = blockIdx.x * 256 + threadIdx.x;
    if (m >= MTOK) return;
    int b = m / HWc, pix = m % HWc;
    int y = pix / Wc, x = pix % Wc;

    float filt[9];
#pragma unroll
    for (int j = 0; j < 9; j++) filt[j] = b2[j];
#pragma unroll
    for (int t = 0; t < 9; t++) {
        int py = y + t / 3 - 1, px = x + t % 3 - 1;
        if (py < 0 || py >= Hc || px < 0 || px >= Wc) continue;
        const float* srow = sf1 + ((size_t)b * HWc + py * Wc + px) * 32;
#pragma unroll
        for (int c4 = 0; c4 < 8; c4++) {
            float4 v = *(const float4*)&srow[c4 * 4];
#pragma unroll
            for (int j = 0; j < 9; j++) {
                const float* wj = ws + j * 288 + (c4 * 4) * 9 + t;
                filt[j] += v.x * wj[0] + v.y * wj[9] + v.z * wj[18] + v.w * wj[27];
            }
        }
    }
    const float* xb = xin + (size_t)b * 3 * HWc;
    float acc = 0.f;
#pragma unroll
    for (int t = 0; t < 9; t++) {
        int py = y + t / 3 - 1, px = x + t % 3 - 1;
        if (py < 0 || py >= Hc || px < 0 || px >= Wc) continue;
        int p = py * Wc + px;
        float s = xb[p] + xb[HWc + p] + xb[2 * HWc + p];
        acc += filt[t] * s;
    }
    fus[m] = acc;
}

// ======== dec2 conv (N=1, K=576) + sigmoid, scalar fp32 ========
__global__ void __launch_bounds__(256)
dec2_k(const float* __restrict__ d1, const float* __restrict__ w,
       const float* __restrict__ b, float* __restrict__ outp) {
    __shared__ float ws[576];
    for (int i = threadIdx.x; i < 576; i += 256) ws[i] = w[i];
    __syncthreads();
    int m = blockIdx.x * 256 + threadIdx.x;
    if (m >= MTOK) return;
    int bb = m / HWc, pix = m % HWc;
    int y = pix / Wc, x = pix % Wc;
    float acc = b[0];
#pragma unroll
    for (int t = 0; t < 9; t++) {
        int py = y + t / 3 - 1, px = x + t % 3 - 1;
        if (py < 0 || py >= Hc || px < 0 || px >= Wc) continue;
        const float* row = d1 + ((size_t)bb * HWc + py * Wc + px) * 64;
#pragma unroll
        for (int c4 = 0; c4 < 16; c4++) {
            float4 v = *(const float4*)&row[c4 * 4];
            const float* wp = ws + (c4 * 4) * 9 + t;
            acc += v.x * wp[0] + v.y * wp[9] + v.z * wp[18] + v.w * wp[27];
        }
    }
    outp[m] = 1.f / (1.f + expf(-acc));
}

template<int BNT, int WMg, int WNg>
static void run_conv512(const float* src, int Cin, const float* Wr, const float* b,
                        float* C, int N, int act) {
    constexpr int SM1 = (2 * 256 * SA + 2 * BNT * SA) * 4;
    constexpr int SM2 = (256 * (BNT + 4)) * 4;
    constexpr int SM = SM1 > SM2 ? SM1 : SM2;
    cudaFuncSetAttribute(conv_gemm512<BNT, WMg, WNg>,
                         cudaFuncAttributeMaxDynamicSharedMemorySize, SM);
    dim3 g((N + BNT - 1) / BNT, MTOK / 256);
    conv_gemm512<BNT, WMg, WNg><<<g, 512, SM>>>(src, Cin, Wr, b, C, N, act);
}

extern "C" void kernel_launch(void* const* d_in, const int* in_sizes, int n_in,
                              void* d_out, int out_size) {
    const float* x        = (const float*)d_in[0];
    const float* enc_w1   = (const float*)d_in[1];
    const float* enc_b1   = (const float*)d_in[2];
    const float* enc_w2   = (const float*)d_in[3];
    const float* enc_b2   = (const float*)d_in[4];
    const float* in_pw    = (const float*)d_in[5];
    const float* in_pb    = (const float*)d_in[6];
    const float* out_pw   = (const float*)d_in[7];
    const float* out_pb   = (const float*)d_in[8];
    const float* ln1_g    = (const float*)d_in[9];
    const float* ln1_b    = (const float*)d_in[10];
    const float* ffn_w1   = (const float*)d_in[11];
    const float* ffn_b1   = (const float*)d_in[12];
    const float* ffn_w2   = (const float*)d_in[13];
    const float* ffn_b2   = (const float*)d_in[14];
    const float* ln2_g    = (const float*)d_in[15];
    const float* ln2_b    = (const float*)d_in[16];
    const float* sf_w1    = (const float*)d_in[17];
    const float* sf_b1    = (const float*)d_in[18];
    const float* sf_w2    = (const float*)d_in[19];
    const float* sf_b2    = (const float*)d_in[20];
    const float* dec_w1   = (const float*)d_in[21];
    const float* dec_b1   = (const float*)d_in[22];
    const float* dec_w2   = (const float*)d_in[23];
    const float* dec_b2   = (const float*)d_in[24];
    float* out = (float*)d_out;

    float *bufA, *t, *qkv, *t1, *t2, *sf1, *fus, *d1, *wr;
    cudaGetSymbolAddress((void**)&bufA, g_bufA);
    cudaGetSymbolAddress((void**)&t,    g_t);
    cudaGetSymbolAddress((void**)&qkv,  g_qkv);
    cudaGetSymbolAddress((void**)&t1,   g_t1);
    cudaGetSymbolAddress((void**)&t2,   g_t2);
    cudaGetSymbolAddress((void**)&sf1,  g_sf1);
    cudaGetSymbolAddress((void**)&fus,  g_fus);
    cudaGetSymbolAddress((void**)&d1,   g_d1);
    cudaGetSymbolAddress((void**)&wr,   g_wr);

    float* wr_enc2 = wr;
    float* wr_sf1  = wr_enc2 + 64 * 576;

    cudaFuncSetAttribute(ffn_fused, cudaFuncAttributeMaxDynamicSharedMemorySize, FFN_SMEM);
    cudaFuncSetAttribute(qkv_gemm, cudaFuncAttributeMaxDynamicSharedMemorySize, QKV_SMEM);
    cudaFuncSetAttribute(oproj_attn_ln, cudaFuncAttributeMaxDynamicSharedMemorySize, OPROJ_SMEM);
    cudaFuncSetAttribute(small_conv<3>, cudaFuncAttributeMaxDynamicSharedMemorySize, SCONV_SMEM);
    cudaFuncSetAttribute(small_conv<1>, cudaFuncAttributeMaxDynamicSharedMemorySize, SCONV_SMEM);

    const int M = MTOK;
    auto blocks = [](long total, int thr) { return (int)((total + thr - 1) / thr); };

    reorder_w<<<blocks(64 * 576, 256), 256>>>(enc_w2, wr_enc2, 64, 64);
    reorder_w<<<blocks(32 * 576, 256), 256>>>(sf_w1, wr_sf1, 32, 64);

    // ---- encoder ----
    { dim3 g(1, M / 256); small_conv<3><<<g, 256, SCONV_SMEM>>>(x, enc_w1, enc_b1, bufA, 1); }
    run_conv512<64, 8, 2>(bufA, 64, wr_enc2, enc_b2, t, 64, 1);

    // ---- transformer ----
    { dim3 g(3, M / 256); qkv_gemm<<<g, 256, QKV_SMEM>>>(t, in_pw, in_pb, qkv, 192); }
    { dim3 g(1, M / 128); oproj_attn_ln<<<g, 256, OPROJ_SMEM>>>(qkv, out_pw, out_pb, t,
                                                                ln1_g, ln1_b, t1); }
    ffn_fused<<<M / FBM, 256, FFN_SMEM>>>(t1, ffn_w1, ffn_b1, ffn_w2, ffn_b2,
                                          ln2_g, ln2_b, t2);

    // ---- spatial filter branch ----
    run_conv512<32, 16, 1>(t2, 64, wr_sf1, sf_b1, sf1, 32, 0);
    sf2_fuse<<<blocks((long)M, 256), 256>>>(sf1, sf_w2, sf_b2, x, fus);

    // ---- decoder ----
    { dim3 g(1, M / 256); small_conv<1><<<g, 256, SCONV_SMEM>>>(fus, dec_w1, dec_b1, d1, 1); }
    dec2_k<<<blocks((long)M, 256), 256>>>(d1, dec_w2, dec_b2, out);
}

// round 15
// speedup vs baseline: 1.0091x; 1.0037x over previous
#include <cuda_runtime.h>
#include <mma.h>
#include <cstdint>
#include <math.h>

using namespace nvcuda;

#define Hc   224
#define Wc   224
#define HWc  (Hc * Wc)
#define Bc   2
#define MTOK (Bc * HWc)      // 100352
#define Ec   64
#define NHc  4
#define DHc  16
#define DFFc 2048

// ---------------- scratch ----------------
__device__ float g_bufA[MTOK * 64];
__device__ float g_t   [MTOK * 64];
__device__ float g_qkv [MTOK * 192];
__device__ float g_t1  [MTOK * 64];
__device__ float g_t2  [MTOK * 64];
__device__ float g_sf1 [MTOK * 32];
__device__ float g_fus [MTOK];
__device__ float g_d1  [MTOK * 64];
__device__ float g_wr  [64 * 576 + 32 * 576];

__device__ __forceinline__ float to_tf32(float x) {
    uint32_t r;
    asm("cvt.rna.tf32.f32 %0, %1;" : "=r"(r) : "f"(x));
    return __uint_as_float(r);
}
__device__ __forceinline__ float4 to_tf32_4(float4 v) {
    return make_float4(to_tf32(v.x), to_tf32(v.y), to_tf32(v.z), to_tf32(v.w));
}

#define SA 36
#define SE 68
#define FSA 76
#define FBM 256
#define FFN_SMEM ((FBM * FSA + 2 * 64 * FSA + 2 * 64 * SE + FBM * SE) * 4)
#define QKV_SMEM ((256 * SE + 64 * SE) * 4)
#define OPROJ_SMEM ((128 * SE + 64 * SE) * 4)
#define SCONV_SMEM ((256 * SE) * 4)

// ============ qkv GEMM: C[M,192] = A[M,64] @ W[192,64]^T + bias, BM=256 ============
__global__ void __launch_bounds__(256)
qkv_gemm(const float* __restrict__ A, const float* __restrict__ W,
         const float* __restrict__ bias, float* __restrict__ C, int N) {
    extern __shared__ float sm[];
    float* As = sm;
    float* Ws = sm + 256 * SE;
    const int tid = threadIdx.x;
    const int warp = tid >> 5;
    const int wm = warp >> 1, wn = warp & 1;
    const size_t m0 = (size_t)blockIdx.y * 256;
    const int n0 = blockIdx.x * 64;

#pragma unroll
    for (int i = tid; i < 256 * 16; i += 256) {
        int row = i >> 4, q = i & 15;
        float4 v = *(const float4*)&A[(m0 + row) * 64 + q * 4];
        *(float4*)&As[row * SE + q * 4] = to_tf32_4(v);
    }
#pragma unroll
    for (int i = tid; i < 64 * 16; i += 256) {
        int n = i >> 4, q = i & 15;
        float4 v = *(const float4*)&W[(size_t)(n0 + n) * 64 + q * 4];
        *(float4*)&Ws[n * SE + q * 4] = to_tf32_4(v);
    }
    __syncthreads();

    wmma::fragment<wmma::accumulator, 16, 16, 8, float> acc[4][2];
#pragma unroll
    for (int i = 0; i < 4; i++)
#pragma unroll
        for (int j = 0; j < 2; j++) wmma::fill_fragment(acc[i][j], 0.f);
#pragma unroll
    for (int ks = 0; ks < 8; ks++) {
        wmma::fragment<wmma::matrix_a, 16, 16, 8, wmma::precision::tf32, wmma::row_major> a[4];
        wmma::fragment<wmma::matrix_b, 16, 16, 8, wmma::precision::tf32, wmma::col_major> b[2];
#pragma unroll
        for (int i = 0; i < 4; i++)
            wmma::load_matrix_sync(a[i], &As[(wm * 64 + i * 16) * SE + ks * 8], SE);
#pragma unroll
        for (int j = 0; j < 2; j++)
            wmma::load_matrix_sync(b[j], &Ws[(wn * 32 + j * 16) * SE + ks * 8], SE);
#pragma unroll
        for (int i = 0; i < 4; i++)
#pragma unroll
            for (int j = 0; j < 2; j++)
                wmma::mma_sync(acc[i][j], a[i], b[j], acc[i][j]);
    }
    __syncthreads();
#pragma unroll
    for (int i = 0; i < 4; i++)
#pragma unroll
        for (int j = 0; j < 2; j++)
            wmma::store_matrix_sync(&As[(wm * 64 + i * 16) * SE + wn * 32 + j * 16],
                                    acc[i][j], SE, wmma::mem_row_major);
    __syncthreads();
    for (int i = tid; i < 256 * 64; i += 256) {
        int r = i >> 6, c = i & 63;
        C[(m0 + r) * N + n0 + c] = As[r * SE + c] + bias[n0 + c];
    }
}

// ======== out_proj fused: attention pre-pass + GEMM(K=64) + residual + LN1 ========
__global__ void __launch_bounds__(256)
oproj_attn_ln(const float* __restrict__ qkv, const float* __restrict__ W,
              const float* __restrict__ bias, const float* __restrict__ res,
              const float* __restrict__ g, const float* __restrict__ be,
              float* __restrict__ outp) {
    extern __shared__ float sm[];
    float* As = sm;
    float* Ws = sm + 128 * SE;
    const int tid = threadIdx.x;
    const int warp = tid >> 5;
    const int lane = tid & 31;
    const int wm = warp >> 1, wn = warp & 1;
    const size_t m0 = (size_t)blockIdx.y * 128;

#pragma unroll
    for (int it = 0; it < 2; it++) {
        int idx = it * 256 + tid;
        int row = idx >> 2, h = idx & 3;
        size_t m = m0 + row;
        int b = (m >= (size_t)HWc) ? 1 : 0;
        int n = (int)(m - (size_t)b * HWc);
        const float* qp = qkv + m * 192 + h * 16;
        const float* k0 = qkv + (size_t)n * 192 + 64 + h * 16;
        const float* k1 = qkv + ((size_t)HWc + n) * 192 + 64 + h * 16;
        const float* v0 = qkv + (size_t)n * 192 + 128 + h * 16;
        const float* v1 = qkv + ((size_t)HWc + n) * 192 + 128 + h * 16;
        float s0 = 0.f, s1 = 0.f;
#pragma unroll
        for (int d = 0; d < 16; d++) { float qv = qp[d]; s0 += qv * k0[d]; s1 += qv * k1[d]; }
        s0 *= 0.25f; s1 *= 0.25f;
        float mx = fmaxf(s0, s1);
        float e0 = expf(s0 - mx), e1 = expf(s1 - mx);
        float inv = 1.f / (e0 + e1);
        float p0 = e0 * inv, p1 = e1 * inv;
#pragma unroll
        for (int d = 0; d < 16; d++)
            As[row * SE + h * 16 + d] = to_tf32(p0 * v0[d] + p1 * v1[d]);
    }
#pragma unroll
    for (int i = tid; i < 64 * 16; i += 256) {
        int n = i >> 4, q = i & 15;
        float4 v = *(const float4*)&W[(size_t)n * 64 + q * 4];
        *(float4*)&Ws[n * SE + q * 4] = to_tf32_4(v);
    }
    __syncthreads();

    wmma::fragment<wmma::accumulator, 16, 16, 8, float> acc[2][2];
#pragma unroll
    for (int i = 0; i < 2; i++)
#pragma unroll
        for (int j = 0; j < 2; j++) wmma::fill_fragment(acc[i][j], 0.f);
#pragma unroll
    for (int ks = 0; ks < 8; ks++) {
        wmma::fragment<wmma::matrix_a, 16, 16, 8, wmma::precision::tf32, wmma::row_major> a[2];
        wmma::fragment<wmma::matrix_b, 16, 16, 8, wmma::precision::tf32, wmma::col_major> b[2];
#pragma unroll
        for (int i = 0; i < 2; i++)
            wmma::load_matrix_sync(a[i], &As[(wm * 32 + i * 16) * SE + ks * 8], SE);
#pragma unroll
        for (int j = 0; j < 2; j++)
            wmma::load_matrix_sync(b[j], &Ws[(wn * 32 + j * 16) * SE + ks * 8], SE);
#pragma unroll
        for (int i = 0; i < 2; i++)
#pragma unroll
            for (int j = 0; j < 2; j++)
                wmma::mma_sync(acc[i][j], a[i], b[j], acc[i][j]);
    }
    __syncthreads();
#pragma unroll
    for (int i = 0; i < 2; i++)
#pragma unroll
        for (int j = 0; j < 2; j++)
            wmma::store_matrix_sync(&As[(wm * 32 + i * 16) * SE + wn * 32 + j * 16],
                                    acc[i][j], SE, wmma::mem_row_major);
    __syncthreads();
    for (int r = warp * 16; r < warp * 16 + 16; r++) {
        size_t m = m0 + r;
        float x0 = As[r * SE + lane] + bias[lane] + res[m * 64 + lane];
        float x1 = As[r * SE + 32 + lane] + bias[32 + lane] + res[m * 64 + 32 + lane];
        float s = x0 + x1;
#pragma unroll
        for (int o = 16; o > 0; o >>= 1) s += __shfl_xor_sync(0xffffffffu, s, o);
        float mu = s * (1.f / 64.f);
        float c0 = x0 - mu, c1 = x1 - mu;
        float sq = c0 * c0 + c1 * c1;
#pragma unroll
        for (int o = 16; o > 0; o >>= 1) sq += __shfl_xor_sync(0xffffffffu, sq, o);
        float rs = rsqrtf(sq * (1.f / 64.f) + 1e-5f);
        outp[m * 64 + lane]      = g[lane] * c0 * rs + be[lane];
        outp[m * 64 + 32 + lane] = g[lane + 32] * c1 * rs + be[lane + 32];
    }
}

// ======== small conv (CIN=3 or 1): implicit im2col, K padded to 32, BM=256 ========
template<int CIN>
__global__ void __launch_bounds__(256)
small_conv(const float* __restrict__ src, const float* __restrict__ W,
           const float* __restrict__ bias, float* __restrict__ C, int act) {
    constexpr int K = CIN * 9;
    extern __shared__ float sm[];
    float* As = sm;
    float* Ws = sm + 256 * SA;
    const int tid = threadIdx.x;
    const int warp = tid >> 5;
    const int wm = warp >> 1, wn = warp & 1;
    const size_t m0 = (size_t)blockIdx.y * 256;

#pragma unroll
    for (int u = 0; u < 8; u++) {
        int i = tid + u * 256;
        int row = i >> 3, q = i & 7;
        int m = (int)m0 + row;
        int b = m / HWc, pix = m % HWc;
        int y = pix / Wc, x = pix % Wc;
        float vv[4];
#pragma unroll
        for (int e = 0; e < 4; e++) {
            int k = q * 4 + e;
            float v = 0.f;
            if (k < K) {
                int ci = k / 9, kk = k % 9;
                int py = y + kk / 3 - 1, px = x + kk % 3 - 1;
                if (py >= 0 && py < Hc && px >= 0 && px < Wc)
                    v = src[((size_t)(b * CIN + ci) * HWc) + py * Wc + px];
            }
            vv[e] = to_tf32(v);
        }
        *(float4*)&As[row * SA + q * 4] = make_float4(vv[0], vv[1], vv[2], vv[3]);
    }
#pragma unroll
    for (int u = 0; u < 2; u++) {
        int i = tid + u * 256;
        int n = i >> 3, q = i & 7;
        float vv[4];
#pragma unroll
        for (int e = 0; e < 4; e++) {
            int k = q * 4 + e;
            vv[e] = (k < K) ? to_tf32(W[(size_t)n * K + k]) : 0.f;
        }
        *(float4*)&Ws[n * SA + q * 4] = make_float4(vv[0], vv[1], vv[2], vv[3]);
    }
    __syncthreads();

    wmma::fragment<wmma::accumulator, 16, 16, 8, float> acc[4][2];
#pragma unroll
    for (int i = 0; i < 4; i++)
#pragma unroll
        for (int j = 0; j < 2; j++) wmma::fill_fragment(acc[i][j], 0.f);
#pragma unroll
    for (int ks = 0; ks < 4; ks++) {
        wmma::fragment<wmma::matrix_a, 16, 16, 8, wmma::precision::tf32, wmma::row_major> a[4];
        wmma::fragment<wmma::matrix_b, 16, 16, 8, wmma::precision::tf32, wmma::col_major> b[2];
#pragma unroll
        for (int i = 0; i < 4; i++)
            wmma::load_matrix_sync(a[i], &As[(wm * 64 + i * 16) * SA + ks * 8], SA);
#pragma unroll
        for (int j = 0; j < 2; j++)
            wmma::load_matrix_sync(b[j], &Ws[(wn * 32 + j * 16) * SA + ks * 8], SA);
#pragma unroll
        for (int i = 0; i < 4; i++)
#pragma unroll
            for (int j = 0; j < 2; j++)
                wmma::mma_sync(acc[i][j], a[i], b[j], acc[i][j]);
    }
    __syncthreads();
#pragma unroll
    for (int i = 0; i < 4; i++)
#pragma unroll
        for (int j = 0; j < 2; j++)
            wmma::store_matrix_sync(&sm[(wm * 64 + i * 16) * SE + wn * 32 + j * 16],
                                    acc[i][j], SE, wmma::mem_row_major);
    __syncthreads();
    for (int i = tid; i < 256 * 64; i += 256) {
        int r = i >> 6, c = i & 63;
        float v = sm[r * SE + c] + bias[c];
        if (act == 1) v = fmaxf(v, 0.f);
        C[(m0 + r) * 64 + c] = v;
    }
}

// ====== conv GEMM, Cin=64, BK=64 (one 3x3 tap per chunk), 512 threads, BM=256 ====
// Warp grid 8x2 (16 warps): FM = 2, FN = BNT/32.
template<int BNT>
__global__ void __launch_bounds__(512)
conv_tap512(const float* __restrict__ src,
            const float* __restrict__ Wr, const float* __restrict__ bias,
            float* __restrict__ C, int N, int act) {
    constexpr int FN = BNT / 32;
    constexpr int SEB = BNT + 4;
    constexpr int BU = (BNT * 16 + 511) / 512;   // B float4s per thread per chunk
    extern __shared__ float sm[];
    float* AsB = sm;                  // 2 x 256 x SE
    float* BsB = sm + 2 * 256 * SE;   // 2 x BNT x SE

    const int tid = threadIdx.x;
    const int warp = tid >> 5;
    const int wm = warp >> 1, wn = warp & 1;     // 8 x 2
    const size_t m0 = (size_t)blockIdx.y * 256;
    const int n0 = blockIdx.x * BNT;
    const int K = 576;

    // hoisted per-thread row info (8 float4 per chunk; rows tid>>4 pattern)
    int baseOff[8];
    int pyx[8];
#pragma unroll
    for (int u = 0; u < 8; u++) {
        int i = tid + u * 512;
        int row = i >> 4, q = i & 15;
        int m = (int)m0 + row;
        int b = m / HWc, pix = m % HWc;
        int y = pix / Wc, x = pix % Wc;
        baseOff[u] = (b * HWc + y * Wc + x) * 64 + q * 4;
        pyx[u] = (y << 16) | x;
    }

    float4 aR[8], bR[BU];
    auto load_glb = [&](int t) {
        const int ky = t / 3 - 1, kx = t % 3 - 1;
        const int kd = (ky * Wc + kx) * 64;
#pragma unroll
        for (int u = 0; u < 8; u++) {
            int y = pyx[u] >> 16, x = pyx[u] & 0xffff;
            int py = y + ky, px = x + kx;
            float4 v = make_float4(0.f, 0.f, 0.f, 0.f);
            if (py >= 0 && py < Hc && px >= 0 && px < Wc)
                v = *(const float4*)&src[baseOff[u] + kd];
            aR[u] = v;
        }
#pragma unroll
        for (int u = 0; u < BU; u++) {
            int i = tid + u * 512;
            float4 v = make_float4(0.f, 0.f, 0.f, 0.f);
            if (i < BNT * 16) {
                int n = i >> 4, q = i & 15;
                int gn = n0 + n;
                if (gn < N) v = *(const float4*)&Wr[(size_t)gn * K + t * 64 + q * 4];
            }
            bR[u] = v;
        }
    };
    auto sts_all = [&](int buf) {
        float* Ab = AsB + buf * 256 * SE;
        float* Bb = BsB + buf * BNT * SE;
#pragma unroll
        for (int u = 0; u < 8; u++) {
            int i = tid + u * 512;
            int row = i >> 4, q = i & 15;
            *(float4*)&Ab[row * SE + q * 4] = to_tf32_4(aR[u]);
        }
#pragma unroll
        for (int u = 0; u < BU; u++) {
            int i = tid + u * 512;
            if (i < BNT * 16) {
                int n = i >> 4, q = i & 15;
                *(float4*)&Bb[n * SE + q * 4] = to_tf32_4(bR[u]);
            }
        }
    };

    wmma::fragment<wmma::accumulator, 16, 16, 8, float> acc[2][FN];
#pragma unroll
    for (int i = 0; i < 2; i++)
#pragma unroll
        for (int j = 0; j < FN; j++) wmma::fill_fragment(acc[i][j], 0.f);

    load_glb(0); sts_all(0);
    __syncthreads();
    for (int t = 0; t < 9; t++) {
        const int buf = t & 1;
        if (t + 1 < 9) load_glb(t + 1);
        float* Ab = AsB + buf * 256 * SE;
        float* Bb = BsB + buf * BNT * SE;
#pragma unroll
        for (int ks = 0; ks < 8; ks++) {
            wmma::fragment<wmma::matrix_a, 16, 16, 8, wmma::precision::tf32, wmma::row_major> a[2];
            wmma::fragment<wmma::matrix_b, 16, 16, 8, wmma::precision::tf32, wmma::col_major> b[FN];
#pragma unroll
            for (int i = 0; i < 2; i++)
                wmma::load_matrix_sync(a[i], &Ab[((wm * 2 + i) * 16) * SE + ks * 8], SE);
#pragma unroll
            for (int j = 0; j < FN; j++)
                wmma::load_matrix_sync(b[j], &Bb[((wn * FN + j) * 16) * SE + ks * 8], SE);
#pragma unroll
            for (int i = 0; i < 2; i++)
#pragma unroll
                for (int j = 0; j < FN; j++)
                    wmma::mma_sync(acc[i][j], a[i], b[j], acc[i][j]);
        }
        if (t + 1 < 9) sts_all((t + 1) & 1);
        __syncthreads();
    }

#pragma unroll
    for (int i = 0; i < 2; i++)
#pragma unroll
        for (int j = 0; j < FN; j++)
            wmma::store_matrix_sync(&sm[((wm * 2 + i) * 16) * SEB + (wn * FN + j) * 16],
                                    acc[i][j], SEB, wmma::mem_row_major);
    __syncthreads();
    for (int i = tid; i < 256 * BNT; i += 512) {
        int r = i / BNT, col = i % BNT;
        int gn = n0 + col;
        if (gn >= N) continue;
        float v = sm[r * SEB + col] + bias[gn];
        if (act == 1) v = fmaxf(v, 0.f);
        C[(m0 + r) * N + gn] = v;
    }
}

// ===== fused FFN + residual + LN2: BM=256, double-buffered W (proven R11) =====
__global__ void __launch_bounds__(256)
ffn_fused(const float* __restrict__ A, const float* __restrict__ W1,
          const float* __restrict__ B1, const float* __restrict__ W2,
          const float* __restrict__ B2,
          const float* __restrict__ g2, const float* __restrict__ be2,
          float* __restrict__ T2out) {
    extern __shared__ float fsm[];
    float* As  = fsm;
    float* W1s = As + FBM * FSA;
    float* W2s = W1s + 2 * 64 * FSA;
    float* Hs  = W2s + 2 * 64 * SE;
    const int tid = threadIdx.x;
    const int warp = tid >> 5;
    const int lane = tid & 31;
    const int wm = warp >> 1, wn = warp & 1;
    const size_t m0 = (size_t)blockIdx.x * FBM;

    float4 wR[4];
    auto loadW1 = [&](int c) {
#pragma unroll
        for (int u = 0; u < 4; u++) {
            int i = tid + u * 256;
            int n = i >> 4, q = i & 15;
            wR[u] = *(const float4*)&W1[((size_t)c * 64 + n) * 64 + q * 4];
        }
    };
    auto stsW1 = [&](int buf, int c) {
        float* d = W1s + buf * 64 * FSA;
#pragma unroll
        for (int u = 0; u < 4; u++) {
            int i = tid + u * 256;
            int n = i >> 4, q = i & 15;
            *(float4*)&d[n * FSA + q * 4] = to_tf32_4(wR[u]);
        }
        if (tid < 64) {
            float bv = to_tf32(__ldg(&B1[(size_t)c * 64 + tid]));
            *(float4*)&d[tid * FSA + 64] = make_float4(bv, 0.f, 0.f, 0.f);
            *(float4*)&d[tid * FSA + 68] = make_float4(0.f, 0.f, 0.f, 0.f);
            *(float4*)&d[tid * FSA + 72] = make_float4(0.f, 0.f, 0.f, 0.f);
        }
    };
    auto loadW2 = [&](int c) {
#pragma unroll
        for (int u = 0; u < 4; u++) {
            int i = tid + u * 256;
            int o = i >> 4, q = i & 15;
            wR[u] = *(const float4*)&W2[(size_t)o * DFFc + c * 64 + q * 4];
        }
    };
    auto stsW2 = [&](int buf) {
        float* d = W2s + buf * 64 * SE;
#pragma unroll
        for (int u = 0; u < 4; u++) {
            int i = tid + u * 256;
            int o = i >> 4, q = i & 15;
            *(float4*)&d[o * SE + q * 4] = to_tf32_4(wR[u]);
        }
    };

#pragma unroll
    for (int i = tid; i < FBM * 16; i += 256) {
        int row = i >> 4, q = i & 15;
        float4 v = *(const float4*)&A[(m0 + row) * 64 + q * 4];
        *(float4*)&As[row * FSA + q * 4] = to_tf32_4(v);
    }
    for (int row = tid; row < FBM; row += 256) {
        *(float4*)&As[row * FSA + 64] = make_float4(1.f, 0.f, 0.f, 0.f);
        *(float4*)&As[row * FSA + 68] = make_float4(0.f, 0.f, 0.f, 0.f);
        *(float4*)&As[row * FSA + 72] = make_float4(0.f, 0.f, 0.f, 0.f);
    }
    loadW1(0); stsW1(0, 0);
    loadW2(0); stsW2(0);
    __syncthreads();

    wmma::fragment<wmma::accumulator, 16, 16, 8, float> out[4][2];
#pragma unroll
    for (int i = 0; i < 4; i++)
#pragma unroll
        for (int j = 0; j < 2; j++) wmma::fill_fragment(out[i][j], 0.f);

    for (int c = 0; c < 32; c++) {
        const int buf = c & 1;
        if (c + 1 < 32) loadW1(c + 1);
        float* W1b = W1s + buf * 64 * FSA;
        float* W2b = W2s + buf * 64 * SE;

        wmma::fragment<wmma::accumulator, 16, 16, 8, float> hacc[4][2];
#pragma unroll
        for (int i = 0; i < 4; i++)
#pragma unroll
            for (int j = 0; j < 2; j++) wmma::fill_fragment(hacc[i][j], 0.f);
#pragma unroll
        for (int ks = 0; ks < 9; ks++) {
            wmma::fragment<wmma::matrix_a, 16, 16, 8, wmma::precision::tf32, wmma::row_major> a[4];
            wmma::fragment<wmma::matrix_b, 16, 16, 8, wmma::precision::tf32, wmma::col_major> b[2];
#pragma unroll
            for (int i = 0; i < 4; i++)
                wmma::load_matrix_sync(a[i], &As[(wm * 64 + i * 16) * FSA + ks * 8], FSA);
#pragma unroll
            for (int j = 0; j < 2; j++)
                wmma::load_matrix_sync(b[j], &W1b[(wn * 32 + j * 16) * FSA + ks * 8], FSA);
#pragma unroll
            for (int i = 0; i < 4; i++)
#pragma unroll
                for (int j = 0; j < 2; j++)
                    wmma::mma_sync(hacc[i][j], a[i], b[j], hacc[i][j]);
        }
#pragma unroll
        for (int i = 0; i < 4; i++)
#pragma unroll
            for (int j = 0; j < 2; j++) {
#pragma unroll
                for (int e = 0; e < hacc[i][j].num_elements; e++)
                    hacc[i][j].x[e] = to_tf32(fmaxf(hacc[i][j].x[e], 0.f));
                wmma::store_matrix_sync(&Hs[(wm * 64 + i * 16) * SE + wn * 32 + j * 16],
                                        hacc[i][j], SE, wmma::mem_row_major);
            }
        if (c + 1 < 32) stsW1((c + 1) & 1, c + 1);
        __syncthreads();

        if (c + 1 < 32) loadW2(c + 1);
#pragma unroll
        for (int ks = 0; ks < 8; ks++) {
            wmma::fragment<wmma::matrix_a, 16, 16, 8, wmma::precision::tf32, wmma::row_major> a[4];
            wmma::fragment<wmma::matrix_b, 16, 16, 8, wmma::precision::tf32, wmma::col_major> b[2];
#pragma unroll
            for (int i = 0; i < 4; i++)
                wmma::load_matrix_sync(a[i], &Hs[(wm * 64 + i * 16) * SE + ks * 8], SE);
#pragma unroll
            for (int j = 0; j < 2; j++)
                wmma::load_matrix_sync(b[j], &W2b[(wn * 32 + j * 16) * SE + ks * 8], SE);
#pragma unroll
            for (int i = 0; i < 4; i++)
#pragma unroll
                for (int j = 0; j < 2; j++)
                    wmma::mma_sync(out[i][j], a[i], b[j], out[i][j]);
        }
        if (c + 1 < 32) stsW2((c + 1) & 1);
        __syncthreads();
    }

#pragma unroll
    for (int i = 0; i < 4; i++)
#pragma unroll
        for (int j = 0; j < 2; j++)
            wmma::store_matrix_sync(&Hs[(wm * 64 + i * 16) * SE + wn * 32 + j * 16],
                                    out[i][j], SE, wmma::mem_row_major);
    __syncthreads();
    for (int r = warp * 32; r < warp * 32 + 32; r++) {
        size_t m = m0 + r;
        float x0 = Hs[r * SE + lane] + B2[lane] + A[m * 64 + lane];
        float x1 = Hs[r * SE + 32 + lane] + B2[32 + lane] + A[m * 64 + 32 + lane];
        float s = x0 + x1;
#pragma unroll
        for (int o = 16; o > 0; o >>= 1) s += __shfl_xor_sync(0xffffffffu, s, o);
        float mu = s * (1.f / 64.f);
        float c0 = x0 - mu, c1 = x1 - mu;
        float sq = c0 * c0 + c1 * c1;
#pragma unroll
        for (int o = 16; o > 0; o >>= 1) sq += __shfl_xor_sync(0xffffffffu, sq, o);
        float rs = rsqrtf(sq * (1.f / 64.f) + 1e-5f);
        T2out[m * 64 + lane]      = g2[lane] * c0 * rs + be2[lane];
        T2out[m * 64 + 32 + lane] = g2[lane + 32] * c1 * rs + be2[lane + 32];
    }
}

// ---------------- weight reorder ----------------
__global__ void reorder_w(const float* __restrict__ in, float* __restrict__ out,
                          int O, int Cin) {
    int K = Cin * 9;
    int i = blockIdx.x * 256 + threadIdx.x;
    if (i >= O * K) return;
    int o = i / K, k = i % K;
    int kk = k / Cin, ci = k % Cin;
    out[(size_t)o * K + k] = in[(size_t)o * K + ci * 9 + kk];
}

// ======== fused sf2 conv (N=9, K=288) + per-pixel adaptive filter, scalar fp32 ====
__global__ void __launch_bounds__(256)
sf2_fuse(const float* __restrict__ sf1, const float* __restrict__ w2,
         const float* __restrict__ b2, const float* __restrict__ xin,
         float* __restrict__ fus) {
    __shared__ float ws[9 * 288];
    for (int i = threadIdx.x; i < 9 * 288; i += 256) ws[i] = w2[i];
    __syncthreads();
    int m = blockIdx.x * 256 + threadIdx.x;
    if (m >= MTOK) return;
    int b = m / HWc, pix = m % HWc;
    int y = pix / Wc, x = pix % Wc;

    float filt[9];
#pragma unroll
    for (int j = 0; j < 9; j++) filt[j] = b2[j];
#pragma unroll
    for (int t = 0; t < 9; t++) {
        int py = y + t / 3 - 1, px = x + t % 3 - 1;
        if (py < 0 || py >= Hc || px < 0 || px >= Wc) continue;
        const float* srow = sf1 + ((size_t)b * HWc + py * Wc + px) * 32;
#pragma unroll
        for (int c4 = 0; c4 < 8; c4++) {
            float4 v = *(const float4*)&srow[c4 * 4];
#pragma unroll
            for (int j = 0; j < 9; j++) {
                const float* wj = ws + j * 288 + (c4 * 4) * 9 + t;
                filt[j] += v.x * wj[0] + v.y * wj[9] + v.z * wj[18] + v.w * wj[27];
            }
        }
    }
    const float* xb = xin + (size_t)b * 3 * HWc;
    float acc = 0.f;
#pragma unroll
    for (int t = 0; t < 9; t++) {
        int py = y + t / 3 - 1, px = x + t % 3 - 1;
        if (py < 0 || py >= Hc || px < 0 || px >= Wc) continue;
        int p = py * Wc + px;
        float s = xb[p] + xb[HWc + p] + xb[2 * HWc + p];
        acc += filt[t] * s;
    }
    fus[m] = acc;
}

// ======== dec2 conv (N=1, K=576) + sigmoid, scalar fp32 ========
__global__ void __launch_bounds__(256)
dec2_k(const float* __restrict__ d1, const float* __restrict__ w,
       const float* __restrict__ b, float* __restrict__ outp) {
    __shared__ float ws[576];
    for (int i = threadIdx.x; i < 576; i += 256) ws[i] = w[i];
    __syncthreads();
    int m = blockIdx.x * 256 + threadIdx.x;
    if (m >= MTOK) return;
    int bb = m / HWc, pix = m % HWc;
    int y = pix / Wc, x = pix % Wc;
    float acc = b[0];
#pragma unroll
    for (int t = 0; t < 9; t++) {
        int py = y + t / 3 - 1, px = x + t % 3 - 1;
        if (py < 0 || py >= Hc || px < 0 || px >= Wc) continue;
        const float* row = d1 + ((size_t)bb * HWc + py * Wc + px) * 64;
#pragma unroll
        for (int c4 = 0; c4 < 16; c4++) {
            float4 v = *(const float4*)&row[c4 * 4];
            const float* wp = ws + (c4 * 4) * 9 + t;
            acc += v.x * wp[0] + v.y * wp[9] + v.z * wp[18] + v.w * wp[27];
        }
    }
    outp[m] = 1.f / (1.f + expf(-acc));
}

template<int BNT>
static void run_conv_tap(const float* src, const float* Wr, const float* b,
                         float* C, int N, int act) {
    constexpr int SM1 = (2 * 256 * SE + 2 * BNT * SE) * 4;
    constexpr int SM2 = (256 * (BNT + 4)) * 4;
    constexpr int SM = SM1 > SM2 ? SM1 : SM2;
    cudaFuncSetAttribute(conv_tap512<BNT>,
                         cudaFuncAttributeMaxDynamicSharedMemorySize, SM);
    dim3 g((N + BNT - 1) / BNT, MTOK / 256);
    conv_tap512<BNT><<<g, 512, SM>>>(src, Wr, b, C, N, act);
}

extern "C" void kernel_launch(void* const* d_in, const int* in_sizes, int n_in,
                              void* d_out, int out_size) {
    const float* x        = (const float*)d_in[0];
    const float* enc_w1   = (const float*)d_in[1];
    const float* enc_b1   = (const float*)d_in[2];
    const float* enc_w2   = (const float*)d_in[3];
    const float* enc_b2   = (const float*)d_in[4];
    const float* in_pw    = (const float*)d_in[5];
    const float* in_pb    = (const float*)d_in[6];
    const float* out_pw   = (const float*)d_in[7];
    const float* out_pb   = (const float*)d_in[8];
    const float* ln1_g    = (const float*)d_in[9];
    const float* ln1_b    = (const float*)d_in[10];
    const float* ffn_w1   = (const float*)d_in[11];
    const float* ffn_b1   = (const float*)d_in[12];
    const float* ffn_w2   = (const float*)d_in[13];
    const float* ffn_b2   = (const float*)d_in[14];
    const float* ln2_g    = (const float*)d_in[15];
    const float* ln2_b    = (const float*)d_in[16];
    const float* sf_w1    = (const float*)d_in[17];
    const float* sf_b1    = (const float*)d_in[18];
    const float* sf_w2    = (const float*)d_in[19];
    const float* sf_b2    = (const float*)d_in[20];
    const float* dec_w1   = (const float*)d_in[21];
    const float* dec_b1   = (const float*)d_in[22];
    const float* dec_w2   = (const float*)d_in[23];
    const float* dec_b2   = (const float*)d_in[24];
    float* out = (float*)d_out;

    float *bufA, *t, *qkv, *t1, *t2, *sf1, *fus, *d1, *wr;
    cudaGetSymbolAddress((void**)&bufA, g_bufA);
    cudaGetSymbolAddress((void**)&t,    g_t);
    cudaGetSymbolAddress((void**)&qkv,  g_qkv);
    cudaGetSymbolAddress((void**)&t1,   g_t1);
    cudaGetSymbolAddress((void**)&t2,   g_t2);
    cudaGetSymbolAddress((void**)&sf1,  g_sf1);
    cudaGetSymbolAddress((void**)&fus,  g_fus);
    cudaGetSymbolAddress((void**)&d1,   g_d1);
    cudaGetSymbolAddress((void**)&wr,   g_wr);

    float* wr_enc2 = wr;
    float* wr_sf1  = wr_enc2 + 64 * 576;

    cudaFuncSetAttribute(ffn_fused, cudaFuncAttributeMaxDynamicSharedMemorySize, FFN_SMEM);
    cudaFuncSetAttribute(qkv_gemm, cudaFuncAttributeMaxDynamicSharedMemorySize, QKV_SMEM);
    cudaFuncSetAttribute(oproj_attn_ln, cudaFuncAttributeMaxDynamicSharedMemorySize, OPROJ_SMEM);
    cudaFuncSetAttribute(small_conv<3>, cudaFuncAttributeMaxDynamicSharedMemorySize, SCONV_SMEM);
    cudaFuncSetAttribute(small_conv<1>, cudaFuncAttributeMaxDynamicSharedMemorySize, SCONV_SMEM);

    const int M = MTOK;
    auto blocks = [](long total, int thr) { return (int)((total + thr - 1) / thr); };

    reorder_w<<<blocks(64 * 576, 256), 256>>>(enc_w2, wr_enc2, 64, 64);
    reorder_w<<<blocks(32 * 576, 256), 256>>>(sf_w1, wr_sf1, 32, 64);

    // ---- encoder ----
    { dim3 g(1, M / 256); small_conv<3><<<g, 256, SCONV_SMEM>>>(x, enc_w1, enc_b1, bufA, 1); }
    run_conv_tap<64>(bufA, wr_enc2, enc_b2, t, 64, 1);

    // ---- transformer ----
    { dim3 g(3, M / 256); qkv_gemm<<<g, 256, QKV_SMEM>>>(t, in_pw, in_pb, qkv, 192); }
    { dim3 g(1, M / 128); oproj_attn_ln<<<g, 256, OPROJ_SMEM>>>(qkv, out_pw, out_pb, t,
                                                                ln1_g, ln1_b, t1); }
    ffn_fused<<<M / FBM, 256, FFN_SMEM>>>(t1, ffn_w1, ffn_b1, ffn_w2, ffn_b2,
                                          ln2_g, ln2_b, t2);

    // ---- spatial filter branch ----
    run_conv_tap<32>(t2, wr_sf1, sf_b1, sf1, 32, 0);
    sf2_fuse<<<blocks((long)M, 256), 256>>>(sf1, sf_w2, sf_b2, x, fus);

    // ---- decoder ----
    { dim3 g(1, M / 256); small_conv<1><<<g, 256, SCONV_SMEM>>>(fus, dec_w1, dec_b1, d1, 1); }
    dec2_k<<<blocks((long)M, 256), 256>>>(d1, dec_w2, dec_b2, out);
}

// round 16
// speedup vs baseline: 1.0468x; 1.0373x over previous
#include <cuda_runtime.h>
#include <mma.h>
#include <cstdint>
#include <math.h>

using namespace nvcuda;

#define Hc   224
#define Wc   224
#define HWc  (Hc * Wc)
#define Bc   2
#define MTOK (Bc * HWc)      // 100352
#define Ec   64
#define NHc  4
#define DHc  16
#define DFFc 2048

// ---------------- scratch ----------------
__device__ float g_bufA[MTOK * 64];
__device__ float g_t   [MTOK * 64];
__device__ float g_qkv [MTOK * 192];
__device__ float g_t1  [MTOK * 64];
__device__ float g_t2  [MTOK * 64];
__device__ float g_sf1 [MTOK * 32];
__device__ float g_fus [MTOK];
__device__ float g_d1  [MTOK * 64];
__device__ float g_wr  [64 * 576 + 32 * 576];

__device__ __forceinline__ float to_tf32(float x) {
    uint32_t r;
    asm("cvt.rna.tf32.f32 %0, %1;" : "=r"(r) : "f"(x));
    return __uint_as_float(r);
}
__device__ __forceinline__ float4 to_tf32_4(float4 v) {
    return make_float4(to_tf32(v.x), to_tf32(v.y), to_tf32(v.z), to_tf32(v.w));
}

#define SA 36
#define SE 68
#define FSA 76
#define FBM 256
#define FFN_SMEM ((FBM * FSA + 2 * 64 * FSA + 2 * 64 * SE + FBM * SE) * 4)
#define QKV_SMEM ((256 * SE + 64 * SE) * 4)
#define OPROJ_SMEM ((128 * SE + 64 * SE) * 4)
#define SCONV_SMEM ((256 * SE) * 4)

// ============ qkv GEMM: C[M,192] = A[M,64] @ W[192,64]^T + bias, BM=256 ============
__global__ void __launch_bounds__(256)
qkv_gemm(const float* __restrict__ A, const float* __restrict__ W,
         const float* __restrict__ bias, float* __restrict__ C, int N) {
    extern __shared__ float sm[];
    float* As = sm;
    float* Ws = sm + 256 * SE;
    const int tid = threadIdx.x;
    const int warp = tid >> 5;
    const int wm = warp >> 1, wn = warp & 1;
    const size_t m0 = (size_t)blockIdx.y * 256;
    const int n0 = blockIdx.x * 64;

#pragma unroll
    for (int i = tid; i < 256 * 16; i += 256) {
        int row = i >> 4, q = i & 15;
        float4 v = *(const float4*)&A[(m0 + row) * 64 + q * 4];
        *(float4*)&As[row * SE + q * 4] = to_tf32_4(v);
    }
#pragma unroll
    for (int i = tid; i < 64 * 16; i += 256) {
        int n = i >> 4, q = i & 15;
        float4 v = *(const float4*)&W[(size_t)(n0 + n) * 64 + q * 4];
        *(float4*)&Ws[n * SE + q * 4] = to_tf32_4(v);
    }
    __syncthreads();

    wmma::fragment<wmma::accumulator, 16, 16, 8, float> acc[4][2];
#pragma unroll
    for (int i = 0; i < 4; i++)
#pragma unroll
        for (int j = 0; j < 2; j++) wmma::fill_fragment(acc[i][j], 0.f);
#pragma unroll
    for (int ks = 0; ks < 8; ks++) {
        wmma::fragment<wmma::matrix_a, 16, 16, 8, wmma::precision::tf32, wmma::row_major> a[4];
        wmma::fragment<wmma::matrix_b, 16, 16, 8, wmma::precision::tf32, wmma::col_major> b[2];
#pragma unroll
        for (int i = 0; i < 4; i++)
            wmma::load_matrix_sync(a[i], &As[(wm * 64 + i * 16) * SE + ks * 8], SE);
#pragma unroll
        for (int j = 0; j < 2; j++)
            wmma::load_matrix_sync(b[j], &Ws[(wn * 32 + j * 16) * SE + ks * 8], SE);
#pragma unroll
        for (int i = 0; i < 4; i++)
#pragma unroll
            for (int j = 0; j < 2; j++)
                wmma::mma_sync(acc[i][j], a[i], b[j], acc[i][j]);
    }
    __syncthreads();
#pragma unroll
    for (int i = 0; i < 4; i++)
#pragma unroll
        for (int j = 0; j < 2; j++)
            wmma::store_matrix_sync(&As[(wm * 64 + i * 16) * SE + wn * 32 + j * 16],
                                    acc[i][j], SE, wmma::mem_row_major);
    __syncthreads();
    for (int i = tid; i < 256 * 64; i += 256) {
        int r = i >> 6, c = i & 63;
        C[(m0 + r) * N + n0 + c] = As[r * SE + c] + bias[n0 + c];
    }
}

// ======== out_proj fused: attention pre-pass (float4) + GEMM + residual + LN1 =====
__global__ void __launch_bounds__(256)
oproj_attn_ln(const float* __restrict__ qkv, const float* __restrict__ W,
              const float* __restrict__ bias, const float* __restrict__ res,
              const float* __restrict__ g, const float* __restrict__ be,
              float* __restrict__ outp) {
    extern __shared__ float sm[];
    float* As = sm;
    float* Ws = sm + 128 * SE;
    const int tid = threadIdx.x;
    const int warp = tid >> 5;
    const int lane = tid & 31;
    const int wm = warp >> 1, wn = warp & 1;
    const size_t m0 = (size_t)blockIdx.y * 128;

#pragma unroll
    for (int it = 0; it < 2; it++) {
        int idx = it * 256 + tid;
        int row = idx >> 2, h = idx & 3;
        size_t m = m0 + row;
        int b = (m >= (size_t)HWc) ? 1 : 0;
        int n = (int)(m - (size_t)b * HWc);
        const float* qp = qkv + m * 192 + h * 16;
        const float* k0 = qkv + (size_t)n * 192 + 64 + h * 16;
        const float* k1 = qkv + ((size_t)HWc + n) * 192 + 64 + h * 16;
        const float* v0 = qkv + (size_t)n * 192 + 128 + h * 16;
        const float* v1 = qkv + ((size_t)HWc + n) * 192 + 128 + h * 16;
        float s0 = 0.f, s1 = 0.f;
#pragma unroll
        for (int d4 = 0; d4 < 4; d4++) {
            float4 q = *(const float4*)&qp[d4 * 4];
            float4 a = *(const float4*)&k0[d4 * 4];
            float4 c = *(const float4*)&k1[d4 * 4];
            s0 += q.x * a.x + q.y * a.y + q.z * a.z + q.w * a.w;
            s1 += q.x * c.x + q.y * c.y + q.z * c.z + q.w * c.w;
        }
        s0 *= 0.25f; s1 *= 0.25f;
        float mx = fmaxf(s0, s1);
        float e0 = expf(s0 - mx), e1 = expf(s1 - mx);
        float inv = 1.f / (e0 + e1);
        float p0 = e0 * inv, p1 = e1 * inv;
#pragma unroll
        for (int d4 = 0; d4 < 4; d4++) {
            float4 a = *(const float4*)&v0[d4 * 4];
            float4 c = *(const float4*)&v1[d4 * 4];
            float4 o = make_float4(p0 * a.x + p1 * c.x, p0 * a.y + p1 * c.y,
                                   p0 * a.z + p1 * c.z, p0 * a.w + p1 * c.w);
            *(float4*)&As[row * SE + h * 16 + d4 * 4] = to_tf32_4(o);
        }
    }
#pragma unroll
    for (int i = tid; i < 64 * 16; i += 256) {
        int n = i >> 4, q = i & 15;
        float4 v = *(const float4*)&W[(size_t)n * 64 + q * 4];
        *(float4*)&Ws[n * SE + q * 4] = to_tf32_4(v);
    }
    __syncthreads();

    wmma::fragment<wmma::accumulator, 16, 16, 8, float> acc[2][2];
#pragma unroll
    for (int i = 0; i < 2; i++)
#pragma unroll
        for (int j = 0; j < 2; j++) wmma::fill_fragment(acc[i][j], 0.f);
#pragma unroll
    for (int ks = 0; ks < 8; ks++) {
        wmma::fragment<wmma::matrix_a, 16, 16, 8, wmma::precision::tf32, wmma::row_major> a[2];
        wmma::fragment<wmma::matrix_b, 16, 16, 8, wmma::precision::tf32, wmma::col_major> b[2];
#pragma unroll
        for (int i = 0; i < 2; i++)
            wmma::load_matrix_sync(a[i], &As[(wm * 32 + i * 16) * SE + ks * 8], SE);
#pragma unroll
        for (int j = 0; j < 2; j++)
            wmma::load_matrix_sync(b[j], &Ws[(wn * 32 + j * 16) * SE + ks * 8], SE);
#pragma unroll
        for (int i = 0; i < 2; i++)
#pragma unroll
            for (int j = 0; j < 2; j++)
                wmma::mma_sync(acc[i][j], a[i], b[j], acc[i][j]);
    }
    __syncthreads();
#pragma unroll
    for (int i = 0; i < 2; i++)
#pragma unroll
        for (int j = 0; j < 2; j++)
            wmma::store_matrix_sync(&As[(wm * 32 + i * 16) * SE + wn * 32 + j * 16],
                                    acc[i][j], SE, wmma::mem_row_major);
    __syncthreads();
    for (int r = warp * 16; r < warp * 16 + 16; r++) {
        size_t m = m0 + r;
        float x0 = As[r * SE + lane] + bias[lane] + res[m * 64 + lane];
        float x1 = As[r * SE + 32 + lane] + bias[32 + lane] + res[m * 64 + 32 + lane];
        float s = x0 + x1;
#pragma unroll
        for (int o = 16; o > 0; o >>= 1) s += __shfl_xor_sync(0xffffffffu, s, o);
        float mu = s * (1.f / 64.f);
        float c0 = x0 - mu, c1 = x1 - mu;
        float sq = c0 * c0 + c1 * c1;
#pragma unroll
        for (int o = 16; o > 0; o >>= 1) sq += __shfl_xor_sync(0xffffffffu, sq, o);
        float rs = rsqrtf(sq * (1.f / 64.f) + 1e-5f);
        outp[m * 64 + lane]      = g[lane] * c0 * rs + be[lane];
        outp[m * 64 + 32 + lane] = g[lane + 32] * c1 * rs + be[lane + 32];
    }
}

// ======== small conv (CIN=3 or 1): implicit im2col, K padded to 32, BM=256 ========
template<int CIN>
__global__ void __launch_bounds__(256)
small_conv(const float* __restrict__ src, const float* __restrict__ W,
           const float* __restrict__ bias, float* __restrict__ C, int act) {
    constexpr int K = CIN * 9;
    extern __shared__ float sm[];
    float* As = sm;
    float* Ws = sm + 256 * SA;
    const int tid = threadIdx.x;
    const int warp = tid >> 5;
    const int wm = warp >> 1, wn = warp & 1;
    const size_t m0 = (size_t)blockIdx.y * 256;

#pragma unroll
    for (int u = 0; u < 8; u++) {
        int i = tid + u * 256;
        int row = i >> 3, q = i & 7;
        int m = (int)m0 + row;
        int b = m / HWc, pix = m % HWc;
        int y = pix / Wc, x = pix % Wc;
        float vv[4];
#pragma unroll
        for (int e = 0; e < 4; e++) {
            int k = q * 4 + e;
            float v = 0.f;
            if (k < K) {
                int ci = k / 9, kk = k % 9;
                int py = y + kk / 3 - 1, px = x + kk % 3 - 1;
                if (py >= 0 && py < Hc && px >= 0 && px < Wc)
                    v = src[((size_t)(b * CIN + ci) * HWc) + py * Wc + px];
            }
            vv[e] = to_tf32(v);
        }
        *(float4*)&As[row * SA + q * 4] = make_float4(vv[0], vv[1], vv[2], vv[3]);
    }
#pragma unroll
    for (int u = 0; u < 2; u++) {
        int i = tid + u * 256;
        int n = i >> 3, q = i & 7;
        float vv[4];
#pragma unroll
        for (int e = 0; e < 4; e++) {
            int k = q * 4 + e;
            vv[e] = (k < K) ? to_tf32(W[(size_t)n * K + k]) : 0.f;
        }
        *(float4*)&Ws[n * SA + q * 4] = make_float4(vv[0], vv[1], vv[2], vv[3]);
    }
    __syncthreads();

    wmma::fragment<wmma::accumulator, 16, 16, 8, float> acc[4][2];
#pragma unroll
    for (int i = 0; i < 4; i++)
#pragma unroll
        for (int j = 0; j < 2; j++) wmma::fill_fragment(acc[i][j], 0.f);
#pragma unroll
    for (int ks = 0; ks < 4; ks++) {
        wmma::fragment<wmma::matrix_a, 16, 16, 8, wmma::precision::tf32, wmma::row_major> a[4];
        wmma::fragment<wmma::matrix_b, 16, 16, 8, wmma::precision::tf32, wmma::col_major> b[2];
#pragma unroll
        for (int i = 0; i < 4; i++)
            wmma::load_matrix_sync(a[i], &As[(wm * 64 + i * 16) * SA + ks * 8], SA);
#pragma unroll
        for (int j = 0; j < 2; j++)
            wmma::load_matrix_sync(b[j], &Ws[(wn * 32 + j * 16) * SA + ks * 8], SA);
#pragma unroll
        for (int i = 0; i < 4; i++)
#pragma unroll
            for (int j = 0; j < 2; j++)
                wmma::mma_sync(acc[i][j], a[i], b[j], acc[i][j]);
    }
    __syncthreads();
#pragma unroll
    for (int i = 0; i < 4; i++)
#pragma unroll
        for (int j = 0; j < 2; j++)
            wmma::store_matrix_sync(&sm[(wm * 64 + i * 16) * SE + wn * 32 + j * 16],
                                    acc[i][j], SE, wmma::mem_row_major);
    __syncthreads();
    for (int i = tid; i < 256 * 64; i += 256) {
        int r = i >> 6, c = i & 63;
        float v = sm[r * SE + c] + bias[c];
        if (act == 1) v = fmaxf(v, 0.f);
        C[(m0 + r) * 64 + c] = v;
    }
}

// ====== conv GEMM, Cin=64, BK=64 (one tap per chunk), 512 threads, BM=256 ======
// Raw fp32 staging (HW truncates to tf32 in MMA; RZ rounding).
template<int BNT>
__global__ void __launch_bounds__(512)
conv_tap512(const float* __restrict__ src,
            const float* __restrict__ Wr, const float* __restrict__ bias,
            float* __restrict__ C, int N, int act) {
    constexpr int FN = BNT / 32;
    constexpr int SEB = BNT + 4;
    constexpr int BU = (BNT * 16 + 511) / 512;
    extern __shared__ float sm[];
    float* AsB = sm;
    float* BsB = sm + 2 * 256 * SE;

    const int tid = threadIdx.x;
    const int warp = tid >> 5;
    const int wm = warp >> 1, wn = warp & 1;
    const size_t m0 = (size_t)blockIdx.y * 256;
    const int n0 = blockIdx.x * BNT;
    const int K = 576;

    int baseOff[8];
    int pyx[8];
#pragma unroll
    for (int u = 0; u < 8; u++) {
        int i = tid + u * 512;
        int row = i >> 4, q = i & 15;
        int m = (int)m0 + row;
        int b = m / HWc, pix = m % HWc;
        int y = pix / Wc, x = pix % Wc;
        baseOff[u] = (b * HWc + y * Wc + x) * 64 + q * 4;
        pyx[u] = (y << 16) | x;
    }

    float4 aR[8], bR[BU];
    auto load_glb = [&](int t) {
        const int ky = t / 3 - 1, kx = t % 3 - 1;
        const int kd = (ky * Wc + kx) * 64;
#pragma unroll
        for (int u = 0; u < 8; u++) {
            int y = pyx[u] >> 16, x = pyx[u] & 0xffff;
            int py = y + ky, px = x + kx;
            float4 v = make_float4(0.f, 0.f, 0.f, 0.f);
            if (py >= 0 && py < Hc && px >= 0 && px < Wc)
                v = *(const float4*)&src[baseOff[u] + kd];
            aR[u] = v;
        }
#pragma unroll
        for (int u = 0; u < BU; u++) {
            int i = tid + u * 512;
            float4 v = make_float4(0.f, 0.f, 0.f, 0.f);
            if (i < BNT * 16) {
                int n = i >> 4, q = i & 15;
                int gn = n0 + n;
                if (gn < N) v = *(const float4*)&Wr[(size_t)gn * K + t * 64 + q * 4];
            }
            bR[u] = v;
        }
    };
    auto sts_all = [&](int buf) {
        float* Ab = AsB + buf * 256 * SE;
        float* Bb = BsB + buf * BNT * SE;
#pragma unroll
        for (int u = 0; u < 8; u++) {
            int i = tid + u * 512;
            int row = i >> 4, q = i & 15;
            *(float4*)&Ab[row * SE + q * 4] = aR[u];     // raw fp32; MMA truncates
        }
#pragma unroll
        for (int u = 0; u < BU; u++) {
            int i = tid + u * 512;
            if (i < BNT * 16) {
                int n = i >> 4, q = i & 15;
                *(float4*)&Bb[n * SE + q * 4] = bR[u];   // raw fp32
            }
        }
    };

    wmma::fragment<wmma::accumulator, 16, 16, 8, float> acc[2][FN];
#pragma unroll
    for (int i = 0; i < 2; i++)
#pragma unroll
        for (int j = 0; j < FN; j++) wmma::fill_fragment(acc[i][j], 0.f);

    load_glb(0); sts_all(0);
    __syncthreads();
    for (int t = 0; t < 9; t++) {
        const int buf = t & 1;
        if (t + 1 < 9) load_glb(t + 1);
        float* Ab = AsB + buf * 256 * SE;
        float* Bb = BsB + buf * BNT * SE;
#pragma unroll
        for (int ks = 0; ks < 8; ks++) {
            wmma::fragment<wmma::matrix_a, 16, 16, 8, wmma::precision::tf32, wmma::row_major> a[2];
            wmma::fragment<wmma::matrix_b, 16, 16, 8, wmma::precision::tf32, wmma::col_major> b[FN];
#pragma unroll
            for (int i = 0; i < 2; i++)
                wmma::load_matrix_sync(a[i], &Ab[((wm * 2 + i) * 16) * SE + ks * 8], SE);
#pragma unroll
            for (int j = 0; j < FN; j++)
                wmma::load_matrix_sync(b[j], &Bb[((wn * FN + j) * 16) * SE + ks * 8], SE);
#pragma unroll
            for (int i = 0; i < 2; i++)
#pragma unroll
                for (int j = 0; j < FN; j++)
                    wmma::mma_sync(acc[i][j], a[i], b[j], acc[i][j]);
        }
        if (t + 1 < 9) sts_all((t + 1) & 1);
        __syncthreads();
    }

#pragma unroll
    for (int i = 0; i < 2; i++)
#pragma unroll
        for (int j = 0; j < FN; j++)
            wmma::store_matrix_sync(&sm[((wm * 2 + i) * 16) * SEB + (wn * FN + j) * 16],
                                    acc[i][j], SEB, wmma::mem_row_major);
    __syncthreads();
    for (int i = tid; i < 256 * BNT; i += 512) {
        int r = i / BNT, col = i % BNT;
        int gn = n0 + col;
        if (gn >= N) continue;
        float v = sm[r * SEB + col] + bias[gn];
        if (act == 1) v = fmaxf(v, 0.f);
        C[(m0 + r) * N + gn] = v;
    }
}

// ===== fused FFN + residual + LN2: BM=256, double-buffered W (proven R11) =====
__global__ void __launch_bounds__(256)
ffn_fused(const float* __restrict__ A, const float* __restrict__ W1,
          const float* __restrict__ B1, const float* __restrict__ W2,
          const float* __restrict__ B2,
          const float* __restrict__ g2, const float* __restrict__ be2,
          float* __restrict__ T2out) {
    extern __shared__ float fsm[];
    float* As  = fsm;
    float* W1s = As + FBM * FSA;
    float* W2s = W1s + 2 * 64 * FSA;
    float* Hs  = W2s + 2 * 64 * SE;
    const int tid = threadIdx.x;
    const int warp = tid >> 5;
    const int lane = tid & 31;
    const int wm = warp >> 1, wn = warp & 1;
    const size_t m0 = (size_t)blockIdx.x * FBM;

    float4 wR[4];
    auto loadW1 = [&](int c) {
#pragma unroll
        for (int u = 0; u < 4; u++) {
            int i = tid + u * 256;
            int n = i >> 4, q = i & 15;
            wR[u] = *(const float4*)&W1[((size_t)c * 64 + n) * 64 + q * 4];
        }
    };
    auto stsW1 = [&](int buf, int c) {
        float* d = W1s + buf * 64 * FSA;
#pragma unroll
        for (int u = 0; u < 4; u++) {
            int i = tid + u * 256;
            int n = i >> 4, q = i & 15;
            *(float4*)&d[n * FSA + q * 4] = to_tf32_4(wR[u]);
        }
        if (tid < 64) {
            float bv = to_tf32(__ldg(&B1[(size_t)c * 64 + tid]));
            *(float4*)&d[tid * FSA + 64] = make_float4(bv, 0.f, 0.f, 0.f);
            *(float4*)&d[tid * FSA + 68] = make_float4(0.f, 0.f, 0.f, 0.f);
            *(float4*)&d[tid * FSA + 72] = make_float4(0.f, 0.f, 0.f, 0.f);
        }
    };
    auto loadW2 = [&](int c) {
#pragma unroll
        for (int u = 0; u < 4; u++) {
            int i = tid + u * 256;
            int o = i >> 4, q = i & 15;
            wR[u] = *(const float4*)&W2[(size_t)o * DFFc + c * 64 + q * 4];
        }
    };
    auto stsW2 = [&](int buf) {
        float* d = W2s + buf * 64 * SE;
#pragma unroll
        for (int u = 0; u < 4; u++) {
            int i = tid + u * 256;
            int o = i >> 4, q = i & 15;
            *(float4*)&d[o * SE + q * 4] = to_tf32_4(wR[u]);
        }
    };

#pragma unroll
    for (int i = tid; i < FBM * 16; i += 256) {
        int row = i >> 4, q = i & 15;
        float4 v = *(const float4*)&A[(m0 + row) * 64 + q * 4];
        *(float4*)&As[row * FSA + q * 4] = to_tf32_4(v);
    }
    for (int row = tid; row < FBM; row += 256) {
        *(float4*)&As[row * FSA + 64] = make_float4(1.f, 0.f, 0.f, 0.f);
        *(float4*)&As[row * FSA + 68] = make_float4(0.f, 0.f, 0.f, 0.f);
        *(float4*)&As[row * FSA + 72] = make_float4(0.f, 0.f, 0.f, 0.f);
    }
    loadW1(0); stsW1(0, 0);
    loadW2(0); stsW2(0);
    __syncthreads();

    wmma::fragment<wmma::accumulator, 16, 16, 8, float> out[4][2];
#pragma unroll
    for (int i = 0; i < 4; i++)
#pragma unroll
        for (int j = 0; j < 2; j++) wmma::fill_fragment(out[i][j], 0.f);

    for (int c = 0; c < 32; c++) {
        const int buf = c & 1;
        if (c + 1 < 32) loadW1(c + 1);
        float* W1b = W1s + buf * 64 * FSA;
        float* W2b = W2s + buf * 64 * SE;

        wmma::fragment<wmma::accumulator, 16, 16, 8, float> hacc[4][2];
#pragma unroll
        for (int i = 0; i < 4; i++)
#pragma unroll
            for (int j = 0; j < 2; j++) wmma::fill_fragment(hacc[i][j], 0.f);
#pragma unroll
        for (int ks = 0; ks < 9; ks++) {
            wmma::fragment<wmma::matrix_a, 16, 16, 8, wmma::precision::tf32, wmma::row_major> a[4];
            wmma::fragment<wmma::matrix_b, 16, 16, 8, wmma::precision::tf32, wmma::col_major> b[2];
#pragma unroll
            for (int i = 0; i < 4; i++)
                wmma::load_matrix_sync(a[i], &As[(wm * 64 + i * 16) * FSA + ks * 8], FSA);
#pragma unroll
            for (int j = 0; j < 2; j++)
                wmma::load_matrix_sync(b[j], &W1b[(wn * 32 + j * 16) * FSA + ks * 8], FSA);
#pragma unroll
            for (int i = 0; i < 4; i++)
#pragma unroll
                for (int j = 0; j < 2; j++)
                    wmma::mma_sync(hacc[i][j], a[i], b[j], hacc[i][j]);
        }
#pragma unroll
        for (int i = 0; i < 4; i++)
#pragma unroll
            for (int j = 0; j < 2; j++) {
#pragma unroll
                for (int e = 0; e < hacc[i][j].num_elements; e++)
                    hacc[i][j].x[e] = to_tf32(fmaxf(hacc[i][j].x[e], 0.f));
                wmma::store_matrix_sync(&Hs[(wm * 64 + i * 16) * SE + wn * 32 + j * 16],
                                        hacc[i][j], SE, wmma::mem_row_major);
            }
        if (c + 1 < 32) stsW1((c + 1) & 1, c + 1);
        __syncthreads();

        if (c + 1 < 32) loadW2(c + 1);
#pragma unroll
        for (int ks = 0; ks < 8; ks++) {
            wmma::fragment<wmma::matrix_a, 16, 16, 8, wmma::precision::tf32, wmma::row_major> a[4];
            wmma::fragment<wmma::matrix_b, 16, 16, 8, wmma::precision::tf32, wmma::col_major> b[2];
#pragma unroll
            for (int i = 0; i < 4; i++)
                wmma::load_matrix_sync(a[i], &Hs[(wm * 64 + i * 16) * SE + ks * 8], SE);
#pragma unroll
            for (int j = 0; j < 2; j++)
                wmma::load_matrix_sync(b[j], &W2b[(wn * 32 + j * 16) * SE + ks * 8], SE);
#pragma unroll
            for (int i = 0; i < 4; i++)
#pragma unroll
                for (int j = 0; j < 2; j++)
                    wmma::mma_sync(out[i][j], a[i], b[j], out[i][j]);
        }
        if (c + 1 < 32) stsW2((c + 1) & 1);
        __syncthreads();
    }

#pragma unroll
    for (int i = 0; i < 4; i++)
#pragma unroll
        for (int j = 0; j < 2; j++)
            wmma::store_matrix_sync(&Hs[(wm * 64 + i * 16) * SE + wn * 32 + j * 16],
                                    out[i][j], SE, wmma::mem_row_major);
    __syncthreads();
    for (int r = warp * 32; r < warp * 32 + 32; r++) {
        size_t m = m0 + r;
        float x0 = Hs[r * SE + lane] + B2[lane] + A[m * 64 + lane];
        float x1 = Hs[r * SE + 32 + lane] + B2[32 + lane] + A[m * 64 + 32 + lane];
        float s = x0 + x1;
#pragma unroll
        for (int o = 16; o > 0; o >>= 1) s += __shfl_xor_sync(0xffffffffu, s, o);
        float mu = s * (1.f / 64.f);
        float c0 = x0 - mu, c1 = x1 - mu;
        float sq = c0 * c0 + c1 * c1;
#pragma unroll
        for (int o = 16; o > 0; o >>= 1) sq += __shfl_xor_sync(0xffffffffu, sq, o);
        float rs = rsqrtf(sq * (1.f / 64.f) + 1e-5f);
        T2out[m * 64 + lane]      = g2[lane] * c0 * rs + be2[lane];
        T2out[m * 64 + 32 + lane] = g2[lane + 32] * c1 * rs + be2[lane + 32];
    }
}

// ---------------- weight reorder ----------------
__global__ void reorder_w(const float* __restrict__ in, float* __restrict__ out,
                          int O, int Cin) {
    int K = Cin * 9;
    int i = blockIdx.x * 256 + threadIdx.x;
    if (i >= O * K) return;
    int o = i / K, k = i % K;
    int kk = k / Cin, ci = k % Cin;
    out[(size_t)o * K + k] = in[(size_t)o * K + ci * 9 + kk];
}

// ======== fused sf2 conv (N=9, K=288) + per-pixel adaptive filter, scalar fp32 ====
__global__ void __launch_bounds__(256)
sf2_fuse(const float* __restrict__ sf1, const float* __restrict__ w2,
         const float* __restrict__ b2, const float* __restrict__ xin,
         float* __restrict__ fus) {
    __shared__ float ws[9 * 288];
    for (int i = threadIdx.x; i < 9 * 288; i += 256) ws[i] = w2[i];
    __syncthreads();
    int m = blockIdx.x * 256 + threadIdx.x;
    if (m >= MTOK) return;
    int b = m / HWc, pix = m % HWc;
    int y = pix / Wc, x = pix % Wc;

    float filt[9];
#pragma unroll
    for (int j = 0; j < 9; j++) filt[j] = b2[j];
#pragma unroll
    for (int t = 0; t < 9; t++) {
        int py = y + t / 3 - 1, px = x + t % 3 - 1;
        if (py < 0 || py >= Hc || px < 0 || px >= Wc) continue;
        const float* srow = sf1 + ((size_t)b * HWc + py * Wc + px) * 32;
#pragma unroll
        for (int c4 = 0; c4 < 8; c4++) {
            float4 v = *(const float4*)&srow[c4 * 4];
#pragma unroll
            for (int j = 0; j < 9; j++) {
                const float* wj = ws + j * 288 + (c4 * 4) * 9 + t;
                filt[j] += v.x * wj[0] + v.y * wj[9] + v.z * wj[18] + v.w * wj[27];
            }
        }
    }
    const float* xb = xin + (size_t)b * 3 * HWc;
    float acc = 0.f;
#pragma unroll
    for (int t = 0; t < 9; t++) {
        int py = y + t / 3 - 1, px = x + t % 3 - 1;
        if (py < 0 || py >= Hc || px < 0 || px >= Wc) continue;
        int p = py * Wc + px;
        float s = xb[p] + xb[HWc + p] + xb[2 * HWc + p];
        acc += filt[t] * s;
    }
    fus[m] = acc;
}

// ======== dec2 conv (N=1, K=576) + sigmoid, scalar fp32 ========
__global__ void __launch_bounds__(256)
dec2_k(const float* __restrict__ d1, const float* __restrict__ w,
       const float* __restrict__ b, float* __restrict__ outp) {
    __shared__ float ws[576];
    for (int i = threadIdx.x; i < 576; i += 256) ws[i] = w[i];
    __syncthreads();
    int m = blockIdx.x * 256 + threadIdx.x;
    if (m >= MTOK) return;
    int bb = m / HWc, pix = m % HWc;
    int y = pix / Wc, x = pix % Wc;
    float acc = b[0];
#pragma unroll
    for (int t = 0; t < 9; t++) {
        int py = y + t / 3 - 1, px = x + t % 3 - 1;
        if (py < 0 || py >= Hc || px < 0 || px >= Wc) continue;
        const float* row = d1 + ((size_t)bb * HWc + py * Wc + px) * 64;
#pragma unroll
        for (int c4 = 0; c4 < 16; c4++) {
            float4 v = *(const float4*)&row[c4 * 4];
            const float* wp = ws + (c4 * 4) * 9 + t;
            acc += v.x * wp[0] + v.y * wp[9] + v.z * wp[18] + v.w * wp[27];
        }
    }
    outp[m] = 1.f / (1.f + expf(-acc));
}

template<int BNT>
static void run_conv_tap(const float* src, const float* Wr, const float* b,
                         float* C, int N, int act) {
    constexpr int SM1 = (2 * 256 * SE + 2 * BNT * SE) * 4;
    constexpr int SM2 = (256 * (BNT + 4)) * 4;
    constexpr int SM = SM1 > SM2 ? SM1 : SM2;
    cudaFuncSetAttribute(conv_tap512<BNT>,
                         cudaFuncAttributeMaxDynamicSharedMemorySize, SM);
    dim3 g((N + BNT - 1) / BNT, MTOK / 256);
    conv_tap512<BNT><<<g, 512, SM>>>(src, Wr, b, C, N, act);
}

extern "C" void kernel_launch(void* const* d_in, const int* in_sizes, int n_in,
                              void* d_out, int out_size) {
    const float* x        = (const float*)d_in[0];
    const float* enc_w1   = (const float*)d_in[1];
    const float* enc_b1   = (const float*)d_in[2];
    const float* enc_w2   = (const float*)d_in[3];
    const float* enc_b2   = (const float*)d_in[4];
    const float* in_pw    = (const float*)d_in[5];
    const float* in_pb    = (const float*)d_in[6];
    const float* out_pw   = (const float*)d_in[7];
    const float* out_pb   = (const float*)d_in[8];
    const float* ln1_g    = (const float*)d_in[9];
    const float* ln1_b    = (const float*)d_in[10];
    const float* ffn_w1   = (const float*)d_in[11];
    const float* ffn_b1   = (const float*)d_in[12];
    const float* ffn_w2   = (const float*)d_in[13];
    const float* ffn_b2   = (const float*)d_in[14];
    const float* ln2_g    = (const float*)d_in[15];
    const float* ln2_b    = (const float*)d_in[16];
    const float* sf_w1    = (const float*)d_in[17];
    const float* sf_b1    = (const float*)d_in[18];
    const float* sf_w2    = (const float*)d_in[19];
    const float* sf_b2    = (const float*)d_in[20];
    const float* dec_w1   = (const float*)d_in[21];
    const float* dec_b1   = (const float*)d_in[22];
    const float* dec_w2   = (const float*)d_in[23];
    const float* dec_b2   = (const float*)d_in[24];
    float* out = (float*)d_out;

    float *bufA, *t, *qkv, *t1, *t2, *sf1, *fus, *d1, *wr;
    cudaGetSymbolAddress((void**)&bufA, g_bufA);
    cudaGetSymbolAddress((void**)&t,    g_t);
    cudaGetSymbolAddress((void**)&qkv,  g_qkv);
    cudaGetSymbolAddress((void**)&t1,   g_t1);
    cudaGetSymbolAddress((void**)&t2,   g_t2);
    cudaGetSymbolAddress((void**)&sf1,  g_sf1);
    cudaGetSymbolAddress((void**)&fus,  g_fus);
    cudaGetSymbolAddress((void**)&d1,   g_d1);
    cudaGetSymbolAddress((void**)&wr,   g_wr);

    float* wr_enc2 = wr;
    float* wr_sf1  = wr_enc2 + 64 * 576;

    cudaFuncSetAttribute(ffn_fused, cudaFuncAttributeMaxDynamicSharedMemorySize, FFN_SMEM);
    cudaFuncSetAttribute(qkv_gemm, cudaFuncAttributeMaxDynamicSharedMemorySize, QKV_SMEM);
    cudaFuncSetAttribute(oproj_attn_ln, cudaFuncAttributeMaxDynamicSharedMemorySize, OPROJ_SMEM);
    cudaFuncSetAttribute(small_conv<3>, cudaFuncAttributeMaxDynamicSharedMemorySize, SCONV_SMEM);
    cudaFuncSetAttribute(small_conv<1>, cudaFuncAttributeMaxDynamicSharedMemorySize, SCONV_SMEM);

    const int M = MTOK;
    auto blocks = [](long total, int thr) { return (int)((total + thr - 1) / thr); };

    reorder_w<<<blocks(64 * 576, 256), 256>>>(enc_w2, wr_enc2, 64, 64);
    reorder_w<<<blocks(32 * 576, 256), 256>>>(sf_w1, wr_sf1, 32, 64);

    // ---- encoder ----
    { dim3 g(1, M / 256); small_conv<3><<<g, 256, SCONV_SMEM>>>(x, enc_w1, enc_b1, bufA, 1); }
    run_conv_tap<64>(bufA, wr_enc2, enc_b2, t, 64, 1);

    // ---- transformer ----
    { dim3 g(3, M / 256); qkv_gemm<<<g, 256, QKV_SMEM>>>(t, in_pw, in_pb, qkv, 192); }
    { dim3 g(1, M / 128); oproj_attn_ln<<<g, 256, OPROJ_SMEM>>>(qkv, out_pw, out_pb, t,
                                                                ln1_g, ln1_b, t1); }
    ffn_fused<<<M / FBM, 256, FFN_SMEM>>>(t1, ffn_w1, ffn_b1, ffn_w2, ffn_b2,
                                          ln2_g, ln2_b, t2);

    // ---- spatial filter branch ----
    run_conv_tap<32>(t2, wr_sf1, sf_b1, sf1, 32, 0);
    sf2_fuse<<<blocks((long)M, 256), 256>>>(sf1, sf_w2, sf_b2, x, fus);

    // ---- decoder ----
    { dim3 g(1, M / 256); small_conv<1><<<g, 256, SCONV_SMEM>>>(fus, dec_w1, dec_b1, d1, 1); }
    dec2_k<<<blocks((long)M, 256), 256>>>(d1, dec_w2, dec_b2, out);
}

// round 17
// speedup vs baseline: 1.0727x; 1.0247x over previous
#include <cuda_runtime.h>
#include <mma.h>
#include <cstdint>
#include <math.h>

using namespace nvcuda;

#define Hc   224
#define Wc   224
#define HWc  (Hc * Wc)
#define Bc   2
#define MTOK (Bc * HWc)      // 100352
#define Ec   64
#define NHc  4
#define DHc  16
#define DFFc 2048

// ---------------- scratch ----------------
__device__ float g_bufA[MTOK * 64];
__device__ float g_t   [MTOK * 64];
__device__ float g_qkv [MTOK * 192];
__device__ float g_t1  [MTOK * 64];
__device__ float g_t2  [MTOK * 64];
__device__ float g_sf1 [MTOK * 32];
__device__ float g_fus [MTOK];
__device__ float g_d1  [MTOK * 64];
__device__ float g_wr  [64 * 576 + 32 * 576];

#define SA 36
#define SE 68
#define FSA 76
#define FBM 256
#define FFN_SMEM ((FBM * FSA + 2 * 64 * FSA + 2 * 64 * SE + FBM * SE) * 4)
#define QKV_SMEM ((256 * SE + 64 * SE) * 4)
#define OPROJ_SMEM ((128 * SE + 64 * SE) * 4)
#define SCONV_SMEM ((256 * SE) * 4)

// NOTE: all WMMA staging is raw fp32 — tf32 MMA truncates (RZ) in hardware.

// ============ qkv GEMM: C[M,192] = A[M,64] @ W[192,64]^T + bias, BM=256 ============
__global__ void __launch_bounds__(256)
qkv_gemm(const float* __restrict__ A, const float* __restrict__ W,
         const float* __restrict__ bias, float* __restrict__ C, int N) {
    extern __shared__ float sm[];
    float* As = sm;
    float* Ws = sm + 256 * SE;
    const int tid = threadIdx.x;
    const int warp = tid >> 5;
    const int wm = warp >> 1, wn = warp & 1;
    const size_t m0 = (size_t)blockIdx.y * 256;
    const int n0 = blockIdx.x * 64;

#pragma unroll
    for (int i = tid; i < 256 * 16; i += 256) {
        int row = i >> 4, q = i & 15;
        *(float4*)&As[row * SE + q * 4] = *(const float4*)&A[(m0 + row) * 64 + q * 4];
    }
#pragma unroll
    for (int i = tid; i < 64 * 16; i += 256) {
        int n = i >> 4, q = i & 15;
        *(float4*)&Ws[n * SE + q * 4] = *(const float4*)&W[(size_t)(n0 + n) * 64 + q * 4];
    }
    __syncthreads();

    wmma::fragment<wmma::accumulator, 16, 16, 8, float> acc[4][2];
#pragma unroll
    for (int i = 0; i < 4; i++)
#pragma unroll
        for (int j = 0; j < 2; j++) wmma::fill_fragment(acc[i][j], 0.f);
#pragma unroll
    for (int ks = 0; ks < 8; ks++) {
        wmma::fragment<wmma::matrix_a, 16, 16, 8, wmma::precision::tf32, wmma::row_major> a[4];
        wmma::fragment<wmma::matrix_b, 16, 16, 8, wmma::precision::tf32, wmma::col_major> b[2];
#pragma unroll
        for (int i = 0; i < 4; i++)
            wmma::load_matrix_sync(a[i], &As[(wm * 64 + i * 16) * SE + ks * 8], SE);
#pragma unroll
        for (int j = 0; j < 2; j++)
            wmma::load_matrix_sync(b[j], &Ws[(wn * 32 + j * 16) * SE + ks * 8], SE);
#pragma unroll
        for (int i = 0; i < 4; i++)
#pragma unroll
            for (int j = 0; j < 2; j++)
                wmma::mma_sync(acc[i][j], a[i], b[j], acc[i][j]);
    }
    __syncthreads();
#pragma unroll
    for (int i = 0; i < 4; i++)
#pragma unroll
        for (int j = 0; j < 2; j++)
            wmma::store_matrix_sync(&As[(wm * 64 + i * 16) * SE + wn * 32 + j * 16],
                                    acc[i][j], SE, wmma::mem_row_major);
    __syncthreads();
    for (int i = tid; i < 256 * 64; i += 256) {
        int r = i >> 6, c = i & 63;
        C[(m0 + r) * N + n0 + c] = As[r * SE + c] + bias[n0 + c];
    }
}

// ======== out_proj fused: attention pre-pass (float4) + GEMM + residual + LN1 =====
__global__ void __launch_bounds__(256)
oproj_attn_ln(const float* __restrict__ qkv, const float* __restrict__ W,
              const float* __restrict__ bias, const float* __restrict__ res,
              const float* __restrict__ g, const float* __restrict__ be,
              float* __restrict__ outp) {
    extern __shared__ float sm[];
    float* As = sm;
    float* Ws = sm + 128 * SE;
    const int tid = threadIdx.x;
    const int warp = tid >> 5;
    const int lane = tid & 31;
    const int wm = warp >> 1, wn = warp & 1;
    const size_t m0 = (size_t)blockIdx.y * 128;

#pragma unroll
    for (int it = 0; it < 2; it++) {
        int idx = it * 256 + tid;
        int row = idx >> 2, h = idx & 3;
        size_t m = m0 + row;
        int b = (m >= (size_t)HWc) ? 1 : 0;
        int n = (int)(m - (size_t)b * HWc);
        const float* qp = qkv + m * 192 + h * 16;
        const float* k0 = qkv + (size_t)n * 192 + 64 + h * 16;
        const float* k1 = qkv + ((size_t)HWc + n) * 192 + 64 + h * 16;
        const float* v0 = qkv + (size_t)n * 192 + 128 + h * 16;
        const float* v1 = qkv + ((size_t)HWc + n) * 192 + 128 + h * 16;
        float s0 = 0.f, s1 = 0.f;
#pragma unroll
        for (int d4 = 0; d4 < 4; d4++) {
            float4 q = *(const float4*)&qp[d4 * 4];
            float4 a = *(const float4*)&k0[d4 * 4];
            float4 c = *(const float4*)&k1[d4 * 4];
            s0 += q.x * a.x + q.y * a.y + q.z * a.z + q.w * a.w;
            s1 += q.x * c.x + q.y * c.y + q.z * c.z + q.w * c.w;
        }
        s0 *= 0.25f; s1 *= 0.25f;
        float mx = fmaxf(s0, s1);
        float e0 = expf(s0 - mx), e1 = expf(s1 - mx);
        float inv = 1.f / (e0 + e1);
        float p0 = e0 * inv, p1 = e1 * inv;
#pragma unroll
        for (int d4 = 0; d4 < 4; d4++) {
            float4 a = *(const float4*)&v0[d4 * 4];
            float4 c = *(const float4*)&v1[d4 * 4];
            float4 o = make_float4(p0 * a.x + p1 * c.x, p0 * a.y + p1 * c.y,
                                   p0 * a.z + p1 * c.z, p0 * a.w + p1 * c.w);
            *(float4*)&As[row * SE + h * 16 + d4 * 4] = o;
        }
    }
#pragma unroll
    for (int i = tid; i < 64 * 16; i += 256) {
        int n = i >> 4, q = i & 15;
        *(float4*)&Ws[n * SE + q * 4] = *(const float4*)&W[(size_t)n * 64 + q * 4];
    }
    __syncthreads();

    wmma::fragment<wmma::accumulator, 16, 16, 8, float> acc[2][2];
#pragma unroll
    for (int i = 0; i < 2; i++)
#pragma unroll
        for (int j = 0; j < 2; j++) wmma::fill_fragment(acc[i][j], 0.f);
#pragma unroll
    for (int ks = 0; ks < 8; ks++) {
        wmma::fragment<wmma::matrix_a, 16, 16, 8, wmma::precision::tf32, wmma::row_major> a[2];
        wmma::fragment<wmma::matrix_b, 16, 16, 8, wmma::precision::tf32, wmma::col_major> b[2];
#pragma unroll
        for (int i = 0; i < 2; i++)
            wmma::load_matrix_sync(a[i], &As[(wm * 32 + i * 16) * SE + ks * 8], SE);
#pragma unroll
        for (int j = 0; j < 2; j++)
            wmma::load_matrix_sync(b[j], &Ws[(wn * 32 + j * 16) * SE + ks * 8], SE);
#pragma unroll
        for (int i = 0; i < 2; i++)
#pragma unroll
            for (int j = 0; j < 2; j++)
                wmma::mma_sync(acc[i][j], a[i], b[j], acc[i][j]);
    }
    __syncthreads();
#pragma unroll
    for (int i = 0; i < 2; i++)
#pragma unroll
        for (int j = 0; j < 2; j++)
            wmma::store_matrix_sync(&As[(wm * 32 + i * 16) * SE + wn * 32 + j * 16],
                                    acc[i][j], SE, wmma::mem_row_major);
    __syncthreads();
    for (int r = warp * 16; r < warp * 16 + 16; r++) {
        size_t m = m0 + r;
        float x0 = As[r * SE + lane] + bias[lane] + res[m * 64 + lane];
        float x1 = As[r * SE + 32 + lane] + bias[32 + lane] + res[m * 64 + 32 + lane];
        float s = x0 + x1;
#pragma unroll
        for (int o = 16; o > 0; o >>= 1) s += __shfl_xor_sync(0xffffffffu, s, o);
        float mu = s * (1.f / 64.f);
        float c0 = x0 - mu, c1 = x1 - mu;
        float sq = c0 * c0 + c1 * c1;
#pragma unroll
        for (int o = 16; o > 0; o >>= 1) sq += __shfl_xor_sync(0xffffffffu, sq, o);
        float rs = rsqrtf(sq * (1.f / 64.f) + 1e-5f);
        outp[m * 64 + lane]      = g[lane] * c0 * rs + be[lane];
        outp[m * 64 + 32 + lane] = g[lane + 32] * c1 * rs + be[lane + 32];
    }
}

// ======== small conv (CIN=3 or 1): implicit im2col, K padded to 32, BM=256 ========
template<int CIN>
__global__ void __launch_bounds__(256)
small_conv(const float* __restrict__ src, const float* __restrict__ W,
           const float* __restrict__ bias, float* __restrict__ C, int act) {
    constexpr int K = CIN * 9;
    extern __shared__ float sm[];
    float* As = sm;
    float* Ws = sm + 256 * SA;
    const int tid = threadIdx.x;
    const int warp = tid >> 5;
    const int wm = warp >> 1, wn = warp & 1;
    const size_t m0 = (size_t)blockIdx.y * 256;

#pragma unroll
    for (int u = 0; u < 8; u++) {
        int i = tid + u * 256;
        int row = i >> 3, q = i & 7;
        int m = (int)m0 + row;
        int b = m / HWc, pix = m % HWc;
        int y = pix / Wc, x = pix % Wc;
        float vv[4];
#pragma unroll
        for (int e = 0; e < 4; e++) {
            int k = q * 4 + e;
            float v = 0.f;
            if (k < K) {
                int ci = k / 9, kk = k % 9;
                int py = y + kk / 3 - 1, px = x + kk % 3 - 1;
                if (py >= 0 && py < Hc && px >= 0 && px < Wc)
                    v = src[((size_t)(b * CIN + ci) * HWc) + py * Wc + px];
            }
            vv[e] = v;
        }
        *(float4*)&As[row * SA + q * 4] = make_float4(vv[0], vv[1], vv[2], vv[3]);
    }
#pragma unroll
    for (int u = 0; u < 2; u++) {
        int i = tid + u * 256;
        int n = i >> 3, q = i & 7;
        float vv[4];
#pragma unroll
        for (int e = 0; e < 4; e++) {
            int k = q * 4 + e;
            vv[e] = (k < K) ? W[(size_t)n * K + k] : 0.f;
        }
        *(float4*)&Ws[n * SA + q * 4] = make_float4(vv[0], vv[1], vv[2], vv[3]);
    }
    __syncthreads();

    wmma::fragment<wmma::accumulator, 16, 16, 8, float> acc[4][2];
#pragma unroll
    for (int i = 0; i < 4; i++)
#pragma unroll
        for (int j = 0; j < 2; j++) wmma::fill_fragment(acc[i][j], 0.f);
#pragma unroll
    for (int ks = 0; ks < 4; ks++) {
        wmma::fragment<wmma::matrix_a, 16, 16, 8, wmma::precision::tf32, wmma::row_major> a[4];
        wmma::fragment<wmma::matrix_b, 16, 16, 8, wmma::precision::tf32, wmma::col_major> b[2];
#pragma unroll
        for (int i = 0; i < 4; i++)
            wmma::load_matrix_sync(a[i], &As[(wm * 64 + i * 16) * SA + ks * 8], SA);
#pragma unroll
        for (int j = 0; j < 2; j++)
            wmma::load_matrix_sync(b[j], &Ws[(wn * 32 + j * 16) * SA + ks * 8], SA);
#pragma unroll
        for (int i = 0; i < 4; i++)
#pragma unroll
            for (int j = 0; j < 2; j++)
                wmma::mma_sync(acc[i][j], a[i], b[j], acc[i][j]);
    }
    __syncthreads();
#pragma unroll
    for (int i = 0; i < 4; i++)
#pragma unroll
        for (int j = 0; j < 2; j++)
            wmma::store_matrix_sync(&sm[(wm * 64 + i * 16) * SE + wn * 32 + j * 16],
                                    acc[i][j], SE, wmma::mem_row_major);
    __syncthreads();
    for (int i = tid; i < 256 * 64; i += 256) {
        int r = i >> 6, c = i & 63;
        float v = sm[r * SE + c] + bias[c];
        if (act == 1) v = fmaxf(v, 0.f);
        C[(m0 + r) * 64 + c] = v;
    }
}

// ====== conv GEMM, Cin=64, BK=64 (one tap per chunk), 512 threads, BM=256 ======
template<int BNT>
__global__ void __launch_bounds__(512)
conv_tap512(const float* __restrict__ src,
            const float* __restrict__ Wr, const float* __restrict__ bias,
            float* __restrict__ C, int N, int act) {
    constexpr int FN = BNT / 32;
    constexpr int SEB = BNT + 4;
    constexpr int BU = (BNT * 16 + 511) / 512;
    extern __shared__ float sm[];
    float* AsB = sm;
    float* BsB = sm + 2 * 256 * SE;

    const int tid = threadIdx.x;
    const int warp = tid >> 5;
    const int wm = warp >> 1, wn = warp & 1;
    const size_t m0 = (size_t)blockIdx.y * 256;
    const int n0 = blockIdx.x * BNT;
    const int K = 576;

    int baseOff[8];
    int pyx[8];
#pragma unroll
    for (int u = 0; u < 8; u++) {
        int i = tid + u * 512;
        int row = i >> 4, q = i & 15;
        int m = (int)m0 + row;
        int b = m / HWc, pix = m % HWc;
        int y = pix / Wc, x = pix % Wc;
        baseOff[u] = (b * HWc + y * Wc + x) * 64 + q * 4;
        pyx[u] = (y << 16) | x;
    }

    float4 aR[8], bR[BU];
    auto load_glb = [&](int t) {
        const int ky = t / 3 - 1, kx = t % 3 - 1;
        const int kd = (ky * Wc + kx) * 64;
#pragma unroll
        for (int u = 0; u < 8; u++) {
            int y = pyx[u] >> 16, x = pyx[u] & 0xffff;
            int py = y + ky, px = x + kx;
            float4 v = make_float4(0.f, 0.f, 0.f, 0.f);
            if (py >= 0 && py < Hc && px >= 0 && px < Wc)
                v = *(const float4*)&src[baseOff[u] + kd];
            aR[u] = v;
        }
#pragma unroll
        for (int u = 0; u < BU; u++) {
            int i = tid + u * 512;
            float4 v = make_float4(0.f, 0.f, 0.f, 0.f);
            if (i < BNT * 16) {
                int n = i >> 4, q = i & 15;
                int gn = n0 + n;
                if (gn < N) v = *(const float4*)&Wr[(size_t)gn * K + t * 64 + q * 4];
            }
            bR[u] = v;
        }
    };
    auto sts_all = [&](int buf) {
        float* Ab = AsB + buf * 256 * SE;
        float* Bb = BsB + buf * BNT * SE;
#pragma unroll
        for (int u = 0; u < 8; u++) {
            int i = tid + u * 512;
            int row = i >> 4, q = i & 15;
            *(float4*)&Ab[row * SE + q * 4] = aR[u];
        }
#pragma unroll
        for (int u = 0; u < BU; u++) {
            int i = tid + u * 512;
            if (i < BNT * 16) {
                int n = i >> 4, q = i & 15;
                *(float4*)&Bb[n * SE + q * 4] = bR[u];
            }
        }
    };

    wmma::fragment<wmma::accumulator, 16, 16, 8, float> acc[2][FN];
#pragma unroll
    for (int i = 0; i < 2; i++)
#pragma unroll
        for (int j = 0; j < FN; j++) wmma::fill_fragment(acc[i][j], 0.f);

    load_glb(0); sts_all(0);
    __syncthreads();
    for (int t = 0; t < 9; t++) {
        const int buf = t & 1;
        if (t + 1 < 9) load_glb(t + 1);
        float* Ab = AsB + buf * 256 * SE;
        float* Bb = BsB + buf * BNT * SE;
#pragma unroll
        for (int ks = 0; ks < 8; ks++) {
            wmma::fragment<wmma::matrix_a, 16, 16, 8, wmma::precision::tf32, wmma::row_major> a[2];
            wmma::fragment<wmma::matrix_b, 16, 16, 8, wmma::precision::tf32, wmma::col_major> b[FN];
#pragma unroll
            for (int i = 0; i < 2; i++)
                wmma::load_matrix_sync(a[i], &Ab[((wm * 2 + i) * 16) * SE + ks * 8], SE);
#pragma unroll
            for (int j = 0; j < FN; j++)
                wmma::load_matrix_sync(b[j], &Bb[((wn * FN + j) * 16) * SE + ks * 8], SE);
#pragma unroll
            for (int i = 0; i < 2; i++)
#pragma unroll
                for (int j = 0; j < FN; j++)
                    wmma::mma_sync(acc[i][j], a[i], b[j], acc[i][j]);
        }
        if (t + 1 < 9) sts_all((t + 1) & 1);
        __syncthreads();
    }

#pragma unroll
    for (int i = 0; i < 2; i++)
#pragma unroll
        for (int j = 0; j < FN; j++)
            wmma::store_matrix_sync(&sm[((wm * 2 + i) * 16) * SEB + (wn * FN + j) * 16],
                                    acc[i][j], SEB, wmma::mem_row_major);
    __syncthreads();
    for (int i = tid; i < 256 * BNT; i += 512) {
        int r = i / BNT, col = i % BNT;
        int gn = n0 + col;
        if (gn >= N) continue;
        float v = sm[r * SEB + col] + bias[gn];
        if (act == 1) v = fmaxf(v, 0.f);
        C[(m0 + r) * N + gn] = v;
    }
}

// ===== fused FFN + residual + LN2: BM=256, raw-fp32 staging everywhere =====
__global__ void __launch_bounds__(256)
ffn_fused(const float* __restrict__ A, const float* __restrict__ W1,
          const float* __restrict__ B1, const float* __restrict__ W2,
          const float* __restrict__ B2,
          const float* __restrict__ g2, const float* __restrict__ be2,
          float* __restrict__ T2out) {
    extern __shared__ float fsm[];
    float* As  = fsm;
    float* W1s = As + FBM * FSA;
    float* W2s = W1s + 2 * 64 * FSA;
    float* Hs  = W2s + 2 * 64 * SE;
    const int tid = threadIdx.x;
    const int warp = tid >> 5;
    const int lane = tid & 31;
    const int wm = warp >> 1, wn = warp & 1;
    const size_t m0 = (size_t)blockIdx.x * FBM;

    float4 wR[4];
    auto loadW1 = [&](int c) {
#pragma unroll
        for (int u = 0; u < 4; u++) {
            int i = tid + u * 256;
            int n = i >> 4, q = i & 15;
            wR[u] = *(const float4*)&W1[((size_t)c * 64 + n) * 64 + q * 4];
        }
    };
    auto stsW1 = [&](int buf, int c) {
        float* d = W1s + buf * 64 * FSA;
#pragma unroll
        for (int u = 0; u < 4; u++) {
            int i = tid + u * 256;
            int n = i >> 4, q = i & 15;
            *(float4*)&d[n * FSA + q * 4] = wR[u];
        }
        if (tid < 64) {
            float bv = __ldg(&B1[(size_t)c * 64 + tid]);
            *(float4*)&d[tid * FSA + 64] = make_float4(bv, 0.f, 0.f, 0.f);
            *(float4*)&d[tid * FSA + 68] = make_float4(0.f, 0.f, 0.f, 0.f);
            *(float4*)&d[tid * FSA + 72] = make_float4(0.f, 0.f, 0.f, 0.f);
        }
    };
    auto loadW2 = [&](int c) {
#pragma unroll
        for (int u = 0; u < 4; u++) {
            int i = tid + u * 256;
            int o = i >> 4, q = i & 15;
            wR[u] = *(const float4*)&W2[(size_t)o * DFFc + c * 64 + q * 4];
        }
    };
    auto stsW2 = [&](int buf) {
        float* d = W2s + buf * 64 * SE;
#pragma unroll
        for (int u = 0; u < 4; u++) {
            int i = tid + u * 256;
            int o = i >> 4, q = i & 15;
            *(float4*)&d[o * SE + q * 4] = wR[u];
        }
    };

#pragma unroll
    for (int i = tid; i < FBM * 16; i += 256) {
        int row = i >> 4, q = i & 15;
        *(float4*)&As[row * FSA + q * 4] = *(const float4*)&A[(m0 + row) * 64 + q * 4];
    }
    for (int row = tid; row < FBM; row += 256) {
        *(float4*)&As[row * FSA + 64] = make_float4(1.f, 0.f, 0.f, 0.f);
        *(float4*)&As[row * FSA + 68] = make_float4(0.f, 0.f, 0.f, 0.f);
        *(float4*)&As[row * FSA + 72] = make_float4(0.f, 0.f, 0.f, 0.f);
    }
    loadW1(0); stsW1(0, 0);
    loadW2(0); stsW2(0);
    __syncthreads();

    wmma::fragment<wmma::accumulator, 16, 16, 8, float> out[4][2];
#pragma unroll
    for (int i = 0; i < 4; i++)
#pragma unroll
        for (int j = 0; j < 2; j++) wmma::fill_fragment(out[i][j], 0.f);

    for (int c = 0; c < 32; c++) {
        const int buf = c & 1;
        if (c + 1 < 32) loadW1(c + 1);
        float* W1b = W1s + buf * 64 * FSA;
        float* W2b = W2s + buf * 64 * SE;

        wmma::fragment<wmma::accumulator, 16, 16, 8, float> hacc[4][2];
#pragma unroll
        for (int i = 0; i < 4; i++)
#pragma unroll
            for (int j = 0; j < 2; j++) wmma::fill_fragment(hacc[i][j], 0.f);
#pragma unroll
        for (int ks = 0; ks < 9; ks++) {
            wmma::fragment<wmma::matrix_a, 16, 16, 8, wmma::precision::tf32, wmma::row_major> a[4];
            wmma::fragment<wmma::matrix_b, 16, 16, 8, wmma::precision::tf32, wmma::col_major> b[2];
#pragma unroll
            for (int i = 0; i < 4; i++)
                wmma::load_matrix_sync(a[i], &As[(wm * 64 + i * 16) * FSA + ks * 8], FSA);
#pragma unroll
            for (int j = 0; j < 2; j++)
                wmma::load_matrix_sync(b[j], &W1b[(wn * 32 + j * 16) * FSA + ks * 8], FSA);
#pragma unroll
            for (int i = 0; i < 4; i++)
#pragma unroll
                for (int j = 0; j < 2; j++)
                    wmma::mma_sync(hacc[i][j], a[i], b[j], hacc[i][j]);
        }
#pragma unroll
        for (int i = 0; i < 4; i++)
#pragma unroll
            for (int j = 0; j < 2; j++) {
#pragma unroll
                for (int e = 0; e < hacc[i][j].num_elements; e++)
                    hacc[i][j].x[e] = fmaxf(hacc[i][j].x[e], 0.f);   // raw fp32 relu
                wmma::store_matrix_sync(&Hs[(wm * 64 + i * 16) * SE + wn * 32 + j * 16],
                                        hacc[i][j], SE, wmma::mem_row_major);
            }
        if (c + 1 < 32) stsW1((c + 1) & 1, c + 1);
        __syncthreads();

        if (c + 1 < 32) loadW2(c + 1);
#pragma unroll
        for (int ks = 0; ks < 8; ks++) {
            wmma::fragment<wmma::matrix_a, 16, 16, 8, wmma::precision::tf32, wmma::row_major> a[4];
            wmma::fragment<wmma::matrix_b, 16, 16, 8, wmma::precision::tf32, wmma::col_major> b[2];
#pragma unroll
            for (int i = 0; i < 4; i++)
                wmma::load_matrix_sync(a[i], &Hs[(wm * 64 + i * 16) * SE + ks * 8], SE);
#pragma unroll
            for (int j = 0; j < 2; j++)
                wmma::load_matrix_sync(b[j], &W2b[(wn * 32 + j * 16) * SE + ks * 8], SE);
#pragma unroll
            for (int i = 0; i < 4; i++)
#pragma unroll
                for (int j = 0; j < 2; j++)
                    wmma::mma_sync(out[i][j], a[i], b[j], out[i][j]);
        }
        if (c + 1 < 32) stsW2((c + 1) & 1);
        __syncthreads();
    }

#pragma unroll
    for (int i = 0; i < 4; i++)
#pragma unroll
        for (int j = 0; j < 2; j++)
            wmma::store_matrix_sync(&Hs[(wm * 64 + i * 16) * SE + wn * 32 + j * 16],
                                    out[i][j], SE, wmma::mem_row_major);
    __syncthreads();
    for (int r = warp * 32; r < warp * 32 + 32; r++) {
        size_t m = m0 + r;
        float x0 = Hs[r * SE + lane] + B2[lane] + A[m * 64 + lane];
        float x1 = Hs[r * SE + 32 + lane] + B2[32 + lane] + A[m * 64 + 32 + lane];
        float s = x0 + x1;
#pragma unroll
        for (int o = 16; o > 0; o >>= 1) s += __shfl_xor_sync(0xffffffffu, s, o);
        float mu = s * (1.f / 64.f);
        float c0 = x0 - mu, c1 = x1 - mu;
        float sq = c0 * c0 + c1 * c1;
#pragma unroll
        for (int o = 16; o > 0; o >>= 1) sq += __shfl_xor_sync(0xffffffffu, sq, o);
        float rs = rsqrtf(sq * (1.f / 64.f) + 1e-5f);
        T2out[m * 64 + lane]      = g2[lane] * c0 * rs + be2[lane];
        T2out[m * 64 + 32 + lane] = g2[lane + 32] * c1 * rs + be2[lane + 32];
    }
}

// ---------------- weight reorder ----------------
__global__ void reorder_w(const float* __restrict__ in, float* __restrict__ out,
                          int O, int Cin) {
    int K = Cin * 9;
    int i = blockIdx.x * 256 + threadIdx.x;
    if (i >= O * K) return;
    int o = i / K, k = i % K;
    int kk = k / Cin, ci = k % Cin;
    out[(size_t)o * K + k] = in[(size_t)o * K + ci * 9 + kk];
}

// ======== fused sf2 conv (N=9, K=288) + per-pixel adaptive filter, scalar fp32 ====
__global__ void __launch_bounds__(256)
sf2_fuse(const float* __restrict__ sf1, const float* __restrict__ w2,
         const float* __restrict__ b2, const float* __restrict__ xin,
         float* __restrict__ fus) {
    __shared__ float ws[9 * 288];
    for (int i = threadIdx.x; i < 9 * 288; i += 256) ws[i] = w2[i];
    __syncthreads();
    int m = blockIdx.x * 256 + threadIdx.x;
    if (m >= MTOK) return;
    int b = m / HWc, pix = m % HWc;
    int y = pix / Wc, x = pix % Wc;

    float filt[9];
#pragma unroll
    for (int j = 0; j < 9; j++) filt[j] = b2[j];
#pragma unroll
    for (int t = 0; t < 9; t++) {
        int py = y + t / 3 - 1, px = x + t % 3 - 1;
        if (py < 0 || py >= Hc || px < 0 || px >= Wc) continue;
        const float* srow = sf1 + ((size_t)b * HWc + py * Wc + px) * 32;
#pragma unroll
        for (int c4 = 0; c4 < 8; c4++) {
            float4 v = *(const float4*)&srow[c4 * 4];
#pragma unroll
            for (int j = 0; j < 9; j++) {
                const float* wj = ws + j * 288 + (c4 * 4) * 9 + t;
                filt[j] += v.x * wj[0] + v.y * wj[9] + v.z * wj[18] + v.w * wj[27];
            }
        }
    }
    const float* xb = xin + (size_t)b * 3 * HWc;
    float acc = 0.f;
#pragma unroll
    for (int t = 0; t < 9; t++) {
        int py = y + t / 3 - 1, px = x + t % 3 - 1;
        if (py < 0 || py >= Hc || px < 0 || px >= Wc) continue;
        int p = py * Wc + px;
        float s = xb[p] + xb[HWc + p] + xb[2 * HWc + p];
        acc += filt[t] * s;
    }
    fus[m] = acc;
}

// ======== dec2 conv (N=1, K=576) + sigmoid, scalar fp32 ========
__global__ void __launch_bounds__(256)
dec2_k(const float* __restrict__ d1, const float* __restrict__ w,
       const float* __restrict__ b, float* __restrict__ outp) {
    __shared__ float ws[576];
    for (int i = threadIdx.x; i < 576; i += 256) ws[i] = w[i];
    __syncthreads();
    int m = blockIdx.x * 256 + threadIdx.x;
    if (m >= MTOK) return;
    int bb = m / HWc, pix = m % HWc;
    int y = pix / Wc, x = pix % Wc;
    float acc = b[0];
#pragma unroll
    for (int t = 0; t < 9; t++) {
        int py = y + t / 3 - 1, px = x + t % 3 - 1;
        if (py < 0 || py >= Hc || px < 0 || px >= Wc) continue;
        const float* row = d1 + ((size_t)bb * HWc + py * Wc + px) * 64;
#pragma unroll
        for (int c4 = 0; c4 < 16; c4++) {
            float4 v = *(const float4*)&row[c4 * 4];
            const float* wp = ws + (c4 * 4) * 9 + t;
            acc += v.x * wp[0] + v.y * wp[9] + v.z * wp[18] + v.w * wp[27];
        }
    }
    outp[m] = 1.f / (1.f + expf(-acc));
}

template<int BNT>
static void run_conv_tap(const float* src, const float* Wr, const float* b,
                         float* C, int N, int act) {
    constexpr int SM1 = (2 * 256 * SE + 2 * BNT * SE) * 4;
    constexpr int SM2 = (256 * (BNT + 4)) * 4;
    constexpr int SM = SM1 > SM2 ? SM1 : SM2;
    cudaFuncSetAttribute(conv_tap512<BNT>,
                         cudaFuncAttributeMaxDynamicSharedMemorySize, SM);
    dim3 g((N + BNT - 1) / BNT, MTOK / 256);
    conv_tap512<BNT><<<g, 512, SM>>>(src, Wr, b, C, N, act);
}

extern "C" void kernel_launch(void* const* d_in, const int* in_sizes, int n_in,
                              void* d_out, int out_size) {
    const float* x        = (const float*)d_in[0];
    const float* enc_w1   = (const float*)d_in[1];
    const float* enc_b1   = (const float*)d_in[2];
    const float* enc_w2   = (const float*)d_in[3];
    const float* enc_b2   = (const float*)d_in[4];
    const float* in_pw    = (const float*)d_in[5];
    const float* in_pb    = (const float*)d_in[6];
    const float* out_pw   = (const float*)d_in[7];
    const float* out_pb   = (const float*)d_in[8];
    const float* ln1_g    = (const float*)d_in[9];
    const float* ln1_b    = (const float*)d_in[10];
    const float* ffn_w1   = (const float*)d_in[11];
    const float* ffn_b1   = (const float*)d_in[12];
    const float* ffn_w2   = (const float*)d_in[13];
    const float* ffn_b2   = (const float*)d_in[14];
    const float* ln2_g    = (const float*)d_in[15];
    const float* ln2_b    = (const float*)d_in[16];
    const float* sf_w1    = (const float*)d_in[17];
    const float* sf_b1    = (const float*)d_in[18];
    const float* sf_w2    = (const float*)d_in[19];
    const float* sf_b2    = (const float*)d_in[20];
    const float* dec_w1   = (const float*)d_in[21];
    const float* dec_b1   = (const float*)d_in[22];
    const float* dec_w2   = (const float*)d_in[23];
    const float* dec_b2   = (const float*)d_in[24];
    float* out = (float*)d_out;

    float *bufA, *t, *qkv, *t1, *t2, *sf1, *fus, *d1, *wr;
    cudaGetSymbolAddress((void**)&bufA, g_bufA);
    cudaGetSymbolAddress((void**)&t,    g_t);
    cudaGetSymbolAddress((void**)&qkv,  g_qkv);
    cudaGetSymbolAddress((void**)&t1,   g_t1);
    cudaGetSymbolAddress((void**)&t2,   g_t2);
    cudaGetSymbolAddress((void**)&sf1,  g_sf1);
    cudaGetSymbolAddress((void**)&fus,  g_fus);
    cudaGetSymbolAddress((void**)&d1,   g_d1);
    cudaGetSymbolAddress((void**)&wr,   g_wr);

    float* wr_enc2 = wr;
    float* wr_sf1  = wr_enc2 + 64 * 576;

    cudaFuncSetAttribute(ffn_fused, cudaFuncAttributeMaxDynamicSharedMemorySize, FFN_SMEM);
    cudaFuncSetAttribute(qkv_gemm, cudaFuncAttributeMaxDynamicSharedMemorySize, QKV_SMEM);
    cudaFuncSetAttribute(oproj_attn_ln, cudaFuncAttributeMaxDynamicSharedMemorySize, OPROJ_SMEM);
    cudaFuncSetAttribute(small_conv<3>, cudaFuncAttributeMaxDynamicSharedMemorySize, SCONV_SMEM);
    cudaFuncSetAttribute(small_conv<1>, cudaFuncAttributeMaxDynamicSharedMemorySize, SCONV_SMEM);

    const int M = MTOK;
    auto blocks = [](long total, int thr) { return (int)((total + thr - 1) / thr); };

    reorder_w<<<blocks(64 * 576, 256), 256>>>(enc_w2, wr_enc2, 64, 64);
    reorder_w<<<blocks(32 * 576, 256), 256>>>(sf_w1, wr_sf1, 32, 64);

    // ---- encoder ----
    { dim3 g(1, M / 256); small_conv<3><<<g, 256, SCONV_SMEM>>>(x, enc_w1, enc_b1, bufA, 1); }
    run_conv_tap<64>(bufA, wr_enc2, enc_b2, t, 64, 1);

    // ---- transformer ----
    { dim3 g(3, M / 256); qkv_gemm<<<g, 256, QKV_SMEM>>>(t, in_pw, in_pb, qkv, 192); }
    { dim3 g(1, M / 128); oproj_attn_ln<<<g, 256, OPROJ_SMEM>>>(qkv, out_pw, out_pb, t,
                                                                ln1_g, ln1_b, t1); }
    ffn_fused<<<M / FBM, 256, FFN_SMEM>>>(t1, ffn_w1, ffn_b1, ffn_w2, ffn_b2,
                                          ln2_g, ln2_b, t2);

    // ---- spatial filter branch ----
    run_conv_tap<32>(t2, wr_sf1, sf_b1, sf1, 32, 0);
    sf2_fuse<<<blocks((long)M, 256), 256>>>(sf1, sf_w2, sf_b2, x, fus);

    // ---- decoder ----
    { dim3 g(1, M / 256); small_conv<1><<<g, 256, SCONV_SMEM>>>(fus, dec_w1, dec_b1, d1, 1); }
    dec2_k<<<blocks((long)M, 256), 256>>>(d1, dec_w2, dec_b2, out);
}